// round 2
// baseline (speedup 1.0000x reference)
#include <cuda_runtime.h>
#include <math.h>

// ---------------- problem dims ----------------
#define LAYERS   4
#define VOCAB    32000
#define DMODEL   2304
#define FFN      9216
#define NHEADS   8
#define KVHEADS  4
#define HDIM     256
#define BATCH    2
#define SEQ      2048
#define MROWS    (BATCH*SEQ)      // 4096
#define WINDOW_SZ 1024
#define ATTN_CAP 50.0f
#define FINAL_CAP 30.0f

// ---------------- static scratch (no allocations allowed) ----------------
__device__ float g_x   [MROWS*DMODEL];
__device__ float g_h   [MROWS*DMODEL];
__device__ float g_q   [MROWS*NHEADS*HDIM];
__device__ float g_k   [MROWS*KVHEADS*HDIM];
__device__ float g_v   [MROWS*KVHEADS*HDIM];
__device__ float g_ao  [MROWS*NHEADS*HDIM];
__device__ float g_gate[MROWS*FFN];
__device__ float g_up  [MROWS*FFN];

// ---------------- helpers ----------------
__device__ __forceinline__ float block_reduce_sum(float v) {
    __shared__ float sh[8];
    int lane = threadIdx.x & 31, wid = threadIdx.x >> 5;
#pragma unroll
    for (int o = 16; o; o >>= 1) v += __shfl_xor_sync(0xffffffffu, v, o);
    if (lane == 0) sh[wid] = v;
    __syncthreads();
    if (wid == 0) {
        float w = (lane < 8) ? sh[lane] : 0.f;
#pragma unroll
        for (int o = 4; o; o >>= 1) w += __shfl_xor_sync(0xffffffffu, w, o);
        if (lane == 0) sh[0] = w;
    }
    __syncthreads();
    return sh[0];
}

// ---------------- embedding ----------------
__global__ void embed_kernel(const int* __restrict__ tokens,
                             const float* __restrict__ emb,
                             float* __restrict__ x, long total) {
    long idx = (long)blockIdx.x * blockDim.x + threadIdx.x;
    if (idx >= total) return;
    long row = idx / DMODEL;
    long d   = idx % DMODEL;
    int tok  = tokens[row];
    x[idx] = emb[(size_t)tok * DMODEL + d] * 48.0f;   // sqrt(2304)=48 exact
}

// ---------------- rmsnorm: out = in * rsqrt(mean(in^2)+eps) * (1+w) ----------------
__global__ void rmsnorm_kernel(const float* __restrict__ in, float* __restrict__ out,
                               const float* __restrict__ w, int cols) {
    long row = blockIdx.x;
    const float* ip = in + row * cols;
    float* op = out + row * cols;
    float s = 0.f;
    for (int i = threadIdx.x; i < cols; i += blockDim.x) { float v = ip[i]; s += v * v; }
    float tot = block_reduce_sum(s);
    float r = rsqrtf(tot / (float)cols + 1e-6f);
    for (int i = threadIdx.x; i < cols; i += blockDim.x)
        op[i] = ip[i] * r * (1.f + w[i]);
}

// ---------------- x += rmsnorm(h, w) ----------------
__global__ void add_rmsnorm_kernel(float* __restrict__ x, const float* __restrict__ h,
                                   const float* __restrict__ w, int cols) {
    long row = blockIdx.x;
    const float* hp = h + row * cols;
    float* xp = x + row * cols;
    float s = 0.f;
    for (int i = threadIdx.x; i < cols; i += blockDim.x) { float v = hp[i]; s += v * v; }
    float tot = block_reduce_sum(s);
    float r = rsqrtf(tot / (float)cols + 1e-6f);
    for (int i = threadIdx.x; i < cols; i += blockDim.x)
        xp[i] += hp[i] * r * (1.f + w[i]);
}

// ---------------- RoPE (split-half) + optional scale ----------------
__global__ void rope_kernel(float* __restrict__ x, int nh, float base,
                            float posDiv, float mul, long total) {
    long idx = (long)blockIdx.x * blockDim.x + threadIdx.x;
    if (idx >= total) return;                       // total = rows * (HDIM/2)
    int i   = (int)(idx & (HDIM/2 - 1));            // 0..127
    long row = idx >> 7;
    int t = (int)((row / nh) % SEQ);
    double frac = (2.0 * (double)i) / (double)HDIM;
    double ts   = exp(frac * log((double)base));
    float ang   = (float)(((double)t / (double)posDiv) / ts);
    float sv, cv;
    sincosf(ang, &sv, &cv);
    float* p = x + (size_t)row * HDIM;
    float x1 = p[i], x2 = p[i + HDIM/2];
    p[i]          = (x1 * cv - x2 * sv) * mul;
    p[i + HDIM/2] = (x2 * cv + x1 * sv) * mul;
}

// ---------------- GeGLU: gate = gelu_tanh(gate) * up ----------------
__global__ void geglu_kernel(float* __restrict__ gate, const float* __restrict__ up, long total) {
    long idx = (long)blockIdx.x * blockDim.x + threadIdx.x;
    if (idx >= total) return;
    float x = gate[idx];
    float x3 = x * x * x;
    float tn = tanhf(0.7978845608028654f * (x + 0.044715f * x3));
    gate[idx] = 0.5f * x * (1.f + tn) * up[idx];
}

// ---------------- generic SGEMM: C = A(MxK) * B, 128x128x8 tile ----------------
// A row-major lda; B: transB=0 -> row-major [K,N] ldb ; transB=1 -> row-major [N,K] ldb (C=A*B^T)
// batched via blockIdx.z with strides. capMode=1 applies 30*tanh(c/30).
__global__ __launch_bounds__(256)
void sgemm_kernel(const float* __restrict__ A, int lda, long sA,
                  const float* __restrict__ B, int ldb, long sB,
                  float* __restrict__ C, int ldc, long sC,
                  int Kd, int transB, int capMode)
{
    __shared__ float As[8][128];
    __shared__ float Bs[8][128];
    const float* Ab = A + (long)blockIdx.z * sA;
    const float* Bb = B + (long)blockIdx.z * sB;
    float*       Cb = C + (long)blockIdx.z * sC;
    int m0 = blockIdx.y * 128;
    int n0 = blockIdx.x * 128;
    int tid = threadIdx.x;
    float acc[8][8];
#pragma unroll
    for (int i = 0; i < 8; i++)
#pragma unroll
        for (int j = 0; j < 8; j++) acc[i][j] = 0.f;

    int arow = tid >> 1, ak4 = (tid & 1) * 4;
    int tx = tid & 15, ty = tid >> 4;

    for (int k0 = 0; k0 < Kd; k0 += 8) {
        float4 av = *(const float4*)(Ab + (size_t)(m0 + arow) * lda + k0 + ak4);
        As[ak4 + 0][arow] = av.x; As[ak4 + 1][arow] = av.y;
        As[ak4 + 2][arow] = av.z; As[ak4 + 3][arow] = av.w;
        if (!transB) {
            int kr = tid >> 5, nc = (tid & 31) * 4;
            float4 bv = *(const float4*)(Bb + (size_t)(k0 + kr) * ldb + n0 + nc);
            Bs[kr][nc + 0] = bv.x; Bs[kr][nc + 1] = bv.y;
            Bs[kr][nc + 2] = bv.z; Bs[kr][nc + 3] = bv.w;
        } else {
            float4 bv = *(const float4*)(Bb + (size_t)(n0 + arow) * ldb + k0 + ak4);
            Bs[ak4 + 0][arow] = bv.x; Bs[ak4 + 1][arow] = bv.y;
            Bs[ak4 + 2][arow] = bv.z; Bs[ak4 + 3][arow] = bv.w;
        }
        __syncthreads();
#pragma unroll
        for (int kk = 0; kk < 8; kk++) {
            float4 a0 = *(float4*)&As[kk][ty * 8];
            float4 a1 = *(float4*)&As[kk][ty * 8 + 4];
            float4 b0 = *(float4*)&Bs[kk][tx * 8];
            float4 b1 = *(float4*)&Bs[kk][tx * 8 + 4];
            float a[8] = {a0.x, a0.y, a0.z, a0.w, a1.x, a1.y, a1.z, a1.w};
            float b[8] = {b0.x, b0.y, b0.z, b0.w, b1.x, b1.y, b1.z, b1.w};
#pragma unroll
            for (int i = 0; i < 8; i++)
#pragma unroll
                for (int j = 0; j < 8; j++) acc[i][j] += a[i] * b[j];
        }
        __syncthreads();
    }
#pragma unroll
    for (int i = 0; i < 8; i++) {
        size_t off = (size_t)(m0 + ty * 8 + i) * ldc + n0 + tx * 8;
        float v[8];
#pragma unroll
        for (int j = 0; j < 8; j++) {
            float c = acc[i][j];
            if (capMode) c = FINAL_CAP * tanhf(c / FINAL_CAP);
            v[j] = c;
        }
        *(float4*)(Cb + off)     = make_float4(v[0], v[1], v[2], v[3]);
        *(float4*)(Cb + off + 4) = make_float4(v[4], v[5], v[6], v[7]);
    }
}

// ---------------- flash attention with soft cap + sliding window ----------------
// grid: (SEQ/16, NHEADS, BATCH), block 256 (8 warps, 2 queries/warp)
#define ST 16
__global__ __launch_bounds__(256)
void attn_kernel(const float* __restrict__ q, const float* __restrict__ k,
                 const float* __restrict__ v, float* __restrict__ out, int isLocal)
{
    __shared__ float ks[ST][HDIM];
    __shared__ float vs[ST][HDIM];
    int b = blockIdx.z, n = blockIdx.y;
    int t0 = blockIdx.x * 16;
    int kh = n >> 1;                       // GQA: group size 2
    int tid = threadIdx.x, wid = tid >> 5, lane = tid & 31;
    int tq = t0 + wid * 2;

    float qr[2][8];
#pragma unroll
    for (int qi = 0; qi < 2; qi++) {
        const float* qp = q + (((size_t)(b * SEQ + tq + qi) * NHEADS + n) * HDIM) + lane * 8;
        float4 a = *(const float4*)qp;
        float4 b4 = *(const float4*)(qp + 4);
        qr[qi][0] = a.x;  qr[qi][1] = a.y;  qr[qi][2] = a.z;  qr[qi][3] = a.w;
        qr[qi][4] = b4.x; qr[qi][5] = b4.y; qr[qi][6] = b4.z; qr[qi][7] = b4.w;
    }
    float m[2] = {-INFINITY, -INFINITY};
    float lsum[2] = {0.f, 0.f};
    float acc[2][8];
#pragma unroll
    for (int qi = 0; qi < 2; qi++)
#pragma unroll
        for (int j = 0; j < 8; j++) acc[qi][j] = 0.f;

    int sEnd = t0 + 15;
    int sLo = 0;
    if (isLocal) { sLo = t0 - (WINDOW_SZ - 1); if (sLo < 0) sLo = 0; }
    sLo &= ~(ST - 1);

    int lr = tid >> 4, lc = tid & 15;      // tile load: 16 rows, 16 thr/row, 4 float4 each
    for (int sB = sLo; sB <= sEnd; sB += ST) {
        const float* kp = k + ((size_t)(b * SEQ + sB + lr) * KVHEADS + kh) * HDIM;
        const float* vp = v + ((size_t)(b * SEQ + sB + lr) * KVHEADS + kh) * HDIM;
#pragma unroll
        for (int j = 0; j < 4; j++) {
            int c = (lc + j * 16) * 4;
            *(float4*)&ks[lr][c] = *(const float4*)(kp + c);
            *(float4*)&vs[lr][c] = *(const float4*)(vp + c);
        }
        __syncthreads();
#pragma unroll 4
        for (int ss = 0; ss < ST; ss++) {
            int s = sB + ss;
            float kk[8];
            *(float4*)&kk[0] = *(float4*)&ks[ss][lane * 8];
            *(float4*)&kk[4] = *(float4*)&ks[ss][lane * 8 + 4];
            float d0 = 0.f, d1 = 0.f;
#pragma unroll
            for (int j = 0; j < 8; j++) { d0 += qr[0][j] * kk[j]; d1 += qr[1][j] * kk[j]; }
#pragma unroll
            for (int o = 16; o; o >>= 1) {
                d0 += __shfl_xor_sync(0xffffffffu, d0, o);
                d1 += __shfl_xor_sync(0xffffffffu, d1, o);
            }
            float vv[8];
            *(float4*)&vv[0] = *(float4*)&vs[ss][lane * 8];
            *(float4*)&vv[4] = *(float4*)&vs[ss][lane * 8 + 4];
#pragma unroll
            for (int qi = 0; qi < 2; qi++) {
                int t = tq + qi;
                bool valid = (s <= t) && (!isLocal || (t - s) < WINDOW_SZ);
                if (valid) {
                    float dd = qi ? d1 : d0;
                    float lg = ATTN_CAP * tanhf(dd / ATTN_CAP);
                    float mn = fmaxf(m[qi], lg);
                    float corr = expf(m[qi] - mn);
                    float p = expf(lg - mn);
                    lsum[qi] = lsum[qi] * corr + p;
#pragma unroll
                    for (int j = 0; j < 8; j++) acc[qi][j] = acc[qi][j] * corr + p * vv[j];
                    m[qi] = mn;
                }
            }
        }
        __syncthreads();
    }
#pragma unroll
    for (int qi = 0; qi < 2; qi++) {
        float inv = 1.f / lsum[qi];
        float* op = out + (((size_t)(b * SEQ + tq + qi) * NHEADS + n) * HDIM) + lane * 8;
        float o0[4] = {acc[qi][0]*inv, acc[qi][1]*inv, acc[qi][2]*inv, acc[qi][3]*inv};
        float o1[4] = {acc[qi][4]*inv, acc[qi][5]*inv, acc[qi][6]*inv, acc[qi][7]*inv};
        *(float4*)op       = make_float4(o0[0], o0[1], o0[2], o0[3]);
        *(float4*)(op + 4) = make_float4(o1[0], o1[1], o1[2], o1[3]);
    }
}

// ---------------- host launcher ----------------
extern "C" void kernel_launch(void* const* d_in, const int* in_sizes, int n_in,
                              void* d_out, int out_size)
{
    const int*   tokens    = (const int*)  d_in[0];
    const float* emb       = (const float*)d_in[1];
    const float* w_q       = (const float*)d_in[2];
    const float* w_kv      = (const float*)d_in[3];
    const float* w_o       = (const float*)d_in[4];
    const float* attn_nrm  = (const float*)d_in[5];
    const float* pattn_nrm = (const float*)d_in[6];
    const float* ffw_nrm   = (const float*)d_in[7];
    const float* pffw_nrm  = (const float*)d_in[8];
    const float* q_nrm     = (const float*)d_in[9];
    const float* k_nrm     = (const float*)d_in[10];
    const float* gate_w    = (const float*)d_in[11];
    const float* down_w    = (const float*)d_in[12];
    const float* final_nrm = (const float*)d_in[13];
    float* out = (float*)d_out;

    float *x, *h, *q, *k, *v, *ao, *gate, *up;
    cudaGetSymbolAddress((void**)&x,    g_x);
    cudaGetSymbolAddress((void**)&h,    g_h);
    cudaGetSymbolAddress((void**)&q,    g_q);
    cudaGetSymbolAddress((void**)&k,    g_k);
    cudaGetSymbolAddress((void**)&v,    g_v);
    cudaGetSymbolAddress((void**)&ao,   g_ao);
    cudaGetSymbolAddress((void**)&gate, g_gate);
    cudaGetSymbolAddress((void**)&up,   g_up);

    // embedding
    {
        long total = (long)MROWS * DMODEL;
        embed_kernel<<<(unsigned)((total + 255) / 256), 256>>>(tokens, emb, x, total);
    }

    for (int l = 0; l < LAYERS; l++) {
        int   isLocal = (l % 2 == 0);
        float base    = isLocal ? 10000.f : 1000000.f;
        float posDiv  = isLocal ? 1.f : 8.f;

        // attn pre-norm
        rmsnorm_kernel<<<MROWS, 256>>>(x, h, attn_nrm + (size_t)l * DMODEL, DMODEL);

        // q projection: 8 batched GEMMs [4096,2304]x[2304,256]
        {
            dim3 grid(HDIM / 128, MROWS / 128, NHEADS);
            sgemm_kernel<<<grid, 256>>>(h, DMODEL, 0,
                w_q + (size_t)l * NHEADS * DMODEL * HDIM, HDIM, (long)DMODEL * HDIM,
                q, NHEADS * HDIM, HDIM, DMODEL, 0, 0);
        }
        // k / v projections: 4 batched GEMMs each
        {
            dim3 grid(HDIM / 128, MROWS / 128, KVHEADS);
            sgemm_kernel<<<grid, 256>>>(h, DMODEL, 0,
                w_kv + (size_t)(l * 2 + 0) * KVHEADS * DMODEL * HDIM, HDIM, (long)DMODEL * HDIM,
                k, KVHEADS * HDIM, HDIM, DMODEL, 0, 0);
            sgemm_kernel<<<grid, 256>>>(h, DMODEL, 0,
                w_kv + (size_t)(l * 2 + 1) * KVHEADS * DMODEL * HDIM, HDIM, (long)DMODEL * HDIM,
                v, KVHEADS * HDIM, HDIM, DMODEL, 0, 0);
        }
        // qk-norm
        rmsnorm_kernel<<<MROWS * NHEADS, 256>>>(q, q, q_nrm + (size_t)l * HDIM, HDIM);
        rmsnorm_kernel<<<MROWS * KVHEADS, 256>>>(k, k, k_nrm + (size_t)l * HDIM, HDIM);
        // rope (+ H^-0.5 scale on q)
        {
            long tq = (long)MROWS * NHEADS * (HDIM / 2);
            long tk = (long)MROWS * KVHEADS * (HDIM / 2);
            rope_kernel<<<(unsigned)((tq + 255) / 256), 256>>>(q, NHEADS,  base, posDiv, 0.0625f, tq);
            rope_kernel<<<(unsigned)((tk + 255) / 256), 256>>>(k, KVHEADS, base, posDiv, 1.0f,    tk);
        }
        // attention
        {
            dim3 grid(SEQ / 16, NHEADS, BATCH);
            attn_kernel<<<grid, 256>>>(q, k, v, ao, isLocal);
        }
        // output projection: [4096,2048]x[2048,2304] -> h
        {
            dim3 grid(DMODEL / 128, MROWS / 128, 1);
            sgemm_kernel<<<grid, 256>>>(ao, NHEADS * HDIM, 0,
                w_o + (size_t)l * NHEADS * HDIM * DMODEL, DMODEL, 0,
                h, DMODEL, 0, NHEADS * HDIM, 0, 0);
        }
        add_rmsnorm_kernel<<<MROWS, 256>>>(x, h, pattn_nrm + (size_t)l * DMODEL, DMODEL);

        // MLP
        rmsnorm_kernel<<<MROWS, 256>>>(x, h, ffw_nrm + (size_t)l * DMODEL, DMODEL);
        {
            dim3 grid(FFN / 128, MROWS / 128, 1);
            sgemm_kernel<<<grid, 256>>>(h, DMODEL, 0,
                gate_w + (size_t)(l * 2 + 0) * DMODEL * FFN, FFN, 0,
                gate, FFN, 0, DMODEL, 0, 0);
            sgemm_kernel<<<grid, 256>>>(h, DMODEL, 0,
                gate_w + (size_t)(l * 2 + 1) * DMODEL * FFN, FFN, 0,
                up, FFN, 0, DMODEL, 0, 0);
        }
        {
            long total = (long)MROWS * FFN;
            geglu_kernel<<<(unsigned)((total + 255) / 256), 256>>>(gate, up, total);
        }
        {
            dim3 grid(DMODEL / 128, MROWS / 128, 1);
            sgemm_kernel<<<grid, 256>>>(gate, FFN, 0,
                down_w + (size_t)l * FFN * DMODEL, DMODEL, 0,
                h, DMODEL, 0, FFN, 0, 0);
        }
        add_rmsnorm_kernel<<<MROWS, 256>>>(x, h, pffw_nrm + (size_t)l * DMODEL, DMODEL);
    }

    // final norm + tied-embedding decode with soft cap
    rmsnorm_kernel<<<MROWS, 256>>>(x, h, final_nrm, DMODEL);
    {
        dim3 grid(VOCAB / 128, MROWS / 128, 1);
        sgemm_kernel<<<grid, 256>>>(h, DMODEL, 0,
            emb, DMODEL, 0,
            out, VOCAB, 0, DMODEL, 1, 1);
    }
}

// round 5
// speedup vs baseline: 2.1612x; 2.1612x over previous
#include <cuda_runtime.h>
#include <math.h>
#include <stdint.h>

// ---------------- problem dims ----------------
#define LAYERS   4
#define VOCAB    32000
#define DMODEL   2304
#define FFN      9216
#define NHEADS   8
#define KVHEADS  4
#define HDIM     256
#define BATCH    2
#define SEQ      2048
#define MROWS    (BATCH*SEQ)      // 4096
#define WINDOW_SZ 1024
#define ATTN_CAP 50.0f
#define FINAL_CAP 30.0f

// ---------------- static scratch (no allocations allowed) ----------------
__device__ float g_x   [MROWS*DMODEL];
__device__ float g_h   [MROWS*DMODEL];
__device__ float g_q   [MROWS*NHEADS*HDIM];
__device__ float g_k   [MROWS*KVHEADS*HDIM];
__device__ float g_v   [MROWS*KVHEADS*HDIM];
__device__ float g_ao  [MROWS*NHEADS*HDIM];
__device__ float g_gate[MROWS*FFN];
__device__ float g_up  [MROWS*FFN];

// ---------------- helpers ----------------
__device__ __forceinline__ float block_reduce_sum(float v) {
    __shared__ float sh[8];
    int lane = threadIdx.x & 31, wid = threadIdx.x >> 5;
#pragma unroll
    for (int o = 16; o; o >>= 1) v += __shfl_xor_sync(0xffffffffu, v, o);
    if (lane == 0) sh[wid] = v;
    __syncthreads();
    if (wid == 0) {
        float w = (lane < 8) ? sh[lane] : 0.f;
#pragma unroll
        for (int o = 4; o; o >>= 1) w += __shfl_xor_sync(0xffffffffu, w, o);
        if (lane == 0) sh[0] = w;
    }
    __syncthreads();
    return sh[0];
}

__device__ __forceinline__ float f_tf32(float f) {
    uint32_t u;
    asm("cvt.rna.tf32.f32 %0, %1;" : "=r"(u) : "f"(f));
    return __uint_as_float(u);
}

// ---------------- embedding ----------------
__global__ void embed_kernel(const int* __restrict__ tokens,
                             const float* __restrict__ emb,
                             float* __restrict__ x, long total) {
    long idx = (long)blockIdx.x * blockDim.x + threadIdx.x;
    if (idx >= total) return;
    long row = idx / DMODEL;
    long d   = idx % DMODEL;
    int tok  = tokens[row];
    x[idx] = emb[(size_t)tok * DMODEL + d] * 48.0f;   // sqrt(2304)=48 exact
}

// ---------------- rmsnorm ----------------
__global__ void rmsnorm_kernel(const float* __restrict__ in, float* __restrict__ out,
                               const float* __restrict__ w, int cols) {
    long row = blockIdx.x;
    const float* ip = in + row * cols;
    float* op = out + row * cols;
    float s = 0.f;
    for (int i = threadIdx.x; i < cols; i += blockDim.x) { float v = ip[i]; s += v * v; }
    float tot = block_reduce_sum(s);
    float r = rsqrtf(tot / (float)cols + 1e-6f);
    for (int i = threadIdx.x; i < cols; i += blockDim.x)
        op[i] = ip[i] * r * (1.f + w[i]);
}

// ---------------- x += rmsnorm(h, w) ----------------
__global__ void add_rmsnorm_kernel(float* __restrict__ x, const float* __restrict__ h,
                                   const float* __restrict__ w, int cols) {
    long row = blockIdx.x;
    const float* hp = h + row * cols;
    float* xp = x + row * cols;
    float s = 0.f;
    for (int i = threadIdx.x; i < cols; i += blockDim.x) { float v = hp[i]; s += v * v; }
    float tot = block_reduce_sum(s);
    float r = rsqrtf(tot / (float)cols + 1e-6f);
    for (int i = threadIdx.x; i < cols; i += blockDim.x)
        xp[i] += hp[i] * r * (1.f + w[i]);
}

// ---------------- RoPE (split-half) + optional scale ----------------
__global__ void rope_kernel(float* __restrict__ x, int nh, float base,
                            float posDiv, float mul, long total) {
    long idx = (long)blockIdx.x * blockDim.x + threadIdx.x;
    if (idx >= total) return;                       // total = rows * (HDIM/2)
    int i   = (int)(idx & (HDIM/2 - 1));            // 0..127
    long row = idx >> 7;
    int t = (int)((row / nh) % SEQ);
    double frac = (2.0 * (double)i) / (double)HDIM;
    double ts   = exp(frac * log((double)base));
    float ang   = (float)(((double)t / (double)posDiv) / ts);
    float sv, cv;
    sincosf(ang, &sv, &cv);
    float* p = x + (size_t)row * HDIM;
    float x1 = p[i], x2 = p[i + HDIM/2];
    p[i]          = (x1 * cv - x2 * sv) * mul;
    p[i + HDIM/2] = (x2 * cv + x1 * sv) * mul;
}

// ---------------- GeGLU ----------------
__global__ void geglu_kernel(float* __restrict__ gate, const float* __restrict__ up, long total) {
    long idx = (long)blockIdx.x * blockDim.x + threadIdx.x;
    if (idx >= total) return;
    float x = gate[idx];
    float x3 = x * x * x;
    float tn = tanhf(0.7978845608028654f * (x + 0.044715f * x3));
    gate[idx] = 0.5f * x * (1.f + tn) * up[idx];
}

// ================= TF32 tensor-core GEMM =================
// C = A(MxK, row-major lda) * B ; transB=0: B row-major [K,N] ; transB=1: B row-major [N,K] (C=A*B^T)
// 128x128x16 CTA tile, 256 threads, warps 2(M) x 4(N), warp tile 64x32.
// mma.sync.aligned.m16n8k8 tf32. Batched via blockIdx.z strides. capMode: 30*tanh(c/30).
#define SMPAD 136

__device__ __forceinline__ void mma_tf32(float& c0, float& c1, float& c2, float& c3,
                                         uint32_t a0, uint32_t a1, uint32_t a2, uint32_t a3,
                                         uint32_t b0, uint32_t b1) {
    asm volatile(
        "mma.sync.aligned.m16n8k8.row.col.f32.tf32.tf32.f32 "
        "{%0,%1,%2,%3}, {%4,%5,%6,%7}, {%8,%9}, {%0,%1,%2,%3};\n"
        : "+f"(c0), "+f"(c1), "+f"(c2), "+f"(c3)
        : "r"(a0), "r"(a1), "r"(a2), "r"(a3), "r"(b0), "r"(b1));
}

__global__ __launch_bounds__(256)
void tgemm_kernel(const float* __restrict__ A, int lda, long sA,
                  const float* __restrict__ B, int ldb, long sB,
                  float* __restrict__ C, int ldc, long sC,
                  int Kd, int transB, int capMode)
{
    __shared__ float As[2][16][SMPAD];
    __shared__ float Bs[2][16][SMPAD];

    const float* Ab = A + (long)blockIdx.z * sA;
    const float* Bb = B + (long)blockIdx.z * sB;
    float*       Cb = C + (long)blockIdx.z * sC;
    const int m0 = blockIdx.y * 128;
    const int n0 = blockIdx.x * 128;
    const int tid = threadIdx.x;
    const int wid = tid >> 5, lane = tid & 31;
    const int g = lane >> 2, t4 = lane & 3;        // groupID, threadID_in_group
    const int wm = (wid & 1) * 64;                 // warp M offset
    const int wn = (wid >> 1) * 32;                // warp N offset

    // A tile load mapping: rows tid>>2 (0..63,+64), k cols (tid&3)*4
    const int arow = tid >> 2;
    const int ak   = (tid & 3) * 4;
    // B tile (transB=0) mapping: row tid>>4 (0..15), col (tid&15)*4 (+64)
    const int bkr  = tid >> 4;
    const int bnc  = (tid & 15) * 4;

    float acc[4][4][4];
#pragma unroll
    for (int i = 0; i < 4; i++)
#pragma unroll
        for (int j = 0; j < 4; j++)
#pragma unroll
            for (int r = 0; r < 4; r++) acc[i][j][r] = 0.f;

    // ---- prologue: load tile 0 into buffer 0 ----
    {
        float4 av0 = *(const float4*)(Ab + (size_t)(m0 + arow) * lda + ak);
        float4 av1 = *(const float4*)(Ab + (size_t)(m0 + arow + 64) * lda + ak);
        As[0][ak + 0][arow] = f_tf32(av0.x); As[0][ak + 1][arow] = f_tf32(av0.y);
        As[0][ak + 2][arow] = f_tf32(av0.z); As[0][ak + 3][arow] = f_tf32(av0.w);
        As[0][ak + 0][arow + 64] = f_tf32(av1.x); As[0][ak + 1][arow + 64] = f_tf32(av1.y);
        As[0][ak + 2][arow + 64] = f_tf32(av1.z); As[0][ak + 3][arow + 64] = f_tf32(av1.w);
        if (!transB) {
            float4 bv0 = *(const float4*)(Bb + (size_t)bkr * ldb + n0 + bnc);
            float4 bv1 = *(const float4*)(Bb + (size_t)bkr * ldb + n0 + bnc + 64);
            Bs[0][bkr][bnc + 0] = f_tf32(bv0.x); Bs[0][bkr][bnc + 1] = f_tf32(bv0.y);
            Bs[0][bkr][bnc + 2] = f_tf32(bv0.z); Bs[0][bkr][bnc + 3] = f_tf32(bv0.w);
            Bs[0][bkr][bnc + 64] = f_tf32(bv1.x); Bs[0][bkr][bnc + 65] = f_tf32(bv1.y);
            Bs[0][bkr][bnc + 66] = f_tf32(bv1.z); Bs[0][bkr][bnc + 67] = f_tf32(bv1.w);
        } else {
            float4 bv0 = *(const float4*)(Bb + (size_t)(n0 + arow) * ldb + ak);
            float4 bv1 = *(const float4*)(Bb + (size_t)(n0 + arow + 64) * ldb + ak);
            Bs[0][ak + 0][arow] = f_tf32(bv0.x); Bs[0][ak + 1][arow] = f_tf32(bv0.y);
            Bs[0][ak + 2][arow] = f_tf32(bv0.z); Bs[0][ak + 3][arow] = f_tf32(bv0.w);
            Bs[0][ak + 0][arow + 64] = f_tf32(bv1.x); Bs[0][ak + 1][arow + 64] = f_tf32(bv1.y);
            Bs[0][ak + 2][arow + 64] = f_tf32(bv1.z); Bs[0][ak + 3][arow + 64] = f_tf32(bv1.w);
        }
    }
    __syncthreads();

    int buf = 0;
    for (int k0 = 0; k0 < Kd; k0 += 16) {
        const bool hasNext = (k0 + 16) < Kd;
        float4 pa0, pa1, pb0, pb1;
        if (hasNext) {
            int kn = k0 + 16;
            pa0 = *(const float4*)(Ab + (size_t)(m0 + arow) * lda + kn + ak);
            pa1 = *(const float4*)(Ab + (size_t)(m0 + arow + 64) * lda + kn + ak);
            if (!transB) {
                pb0 = *(const float4*)(Bb + (size_t)(kn + bkr) * ldb + n0 + bnc);
                pb1 = *(const float4*)(Bb + (size_t)(kn + bkr) * ldb + n0 + bnc + 64);
            } else {
                pb0 = *(const float4*)(Bb + (size_t)(n0 + arow) * ldb + kn + ak);
                pb1 = *(const float4*)(Bb + (size_t)(n0 + arow + 64) * ldb + kn + ak);
            }
        }

        // ---- compute on current buffer ----
#pragma unroll
        for (int ks = 0; ks < 2; ks++) {
            const int kb = ks * 8;
            uint32_t afr[4][4];
            uint32_t bfr[4][2];
#pragma unroll
            for (int i = 0; i < 4; i++) {
                const int mr = wm + i * 16;
                afr[i][0] = __float_as_uint(As[buf][kb + t4    ][mr + g]);
                afr[i][1] = __float_as_uint(As[buf][kb + t4    ][mr + g + 8]);
                afr[i][2] = __float_as_uint(As[buf][kb + t4 + 4][mr + g]);
                afr[i][3] = __float_as_uint(As[buf][kb + t4 + 4][mr + g + 8]);
            }
#pragma unroll
            for (int j = 0; j < 4; j++) {
                const int nc = wn + j * 8;
                bfr[j][0] = __float_as_uint(Bs[buf][kb + t4    ][nc + g]);
                bfr[j][1] = __float_as_uint(Bs[buf][kb + t4 + 4][nc + g]);
            }
#pragma unroll
            for (int i = 0; i < 4; i++)
#pragma unroll
                for (int j = 0; j < 4; j++)
                    mma_tf32(acc[i][j][0], acc[i][j][1], acc[i][j][2], acc[i][j][3],
                             afr[i][0], afr[i][1], afr[i][2], afr[i][3],
                             bfr[j][0], bfr[j][1]);
        }

        if (hasNext) {
            int nb = buf ^ 1;
            As[nb][ak + 0][arow] = f_tf32(pa0.x); As[nb][ak + 1][arow] = f_tf32(pa0.y);
            As[nb][ak + 2][arow] = f_tf32(pa0.z); As[nb][ak + 3][arow] = f_tf32(pa0.w);
            As[nb][ak + 0][arow + 64] = f_tf32(pa1.x); As[nb][ak + 1][arow + 64] = f_tf32(pa1.y);
            As[nb][ak + 2][arow + 64] = f_tf32(pa1.z); As[nb][ak + 3][arow + 64] = f_tf32(pa1.w);
            if (!transB) {
                Bs[nb][bkr][bnc + 0] = f_tf32(pb0.x); Bs[nb][bkr][bnc + 1] = f_tf32(pb0.y);
                Bs[nb][bkr][bnc + 2] = f_tf32(pb0.z); Bs[nb][bkr][bnc + 3] = f_tf32(pb0.w);
                Bs[nb][bkr][bnc + 64] = f_tf32(pb1.x); Bs[nb][bkr][bnc + 65] = f_tf32(pb1.y);
                Bs[nb][bkr][bnc + 66] = f_tf32(pb1.z); Bs[nb][bkr][bnc + 67] = f_tf32(pb1.w);
            } else {
                Bs[nb][ak + 0][arow] = f_tf32(pb0.x); Bs[nb][ak + 1][arow] = f_tf32(pb0.y);
                Bs[nb][ak + 2][arow] = f_tf32(pb0.z); Bs[nb][ak + 3][arow] = f_tf32(pb0.w);
                Bs[nb][ak + 0][arow + 64] = f_tf32(pb1.x); Bs[nb][ak + 1][arow + 64] = f_tf32(pb1.y);
                Bs[nb][ak + 2][arow + 64] = f_tf32(pb1.z); Bs[nb][ak + 3][arow + 64] = f_tf32(pb1.w);
            }
        }
        __syncthreads();
        buf ^= 1;
    }

    // ---- epilogue ----
#pragma unroll
    for (int i = 0; i < 4; i++) {
#pragma unroll
        for (int j = 0; j < 4; j++) {
            int row0 = m0 + wm + i * 16 + g;
            int col  = n0 + wn + j * 8 + 2 * t4;
            float c0 = acc[i][j][0], c1 = acc[i][j][1];
            float c2 = acc[i][j][2], c3 = acc[i][j][3];
            if (capMode) {
                c0 = FINAL_CAP * tanhf(c0 / FINAL_CAP);
                c1 = FINAL_CAP * tanhf(c1 / FINAL_CAP);
                c2 = FINAL_CAP * tanhf(c2 / FINAL_CAP);
                c3 = FINAL_CAP * tanhf(c3 / FINAL_CAP);
            }
            *(float2*)(Cb + (size_t)row0 * ldc + col)       = make_float2(c0, c1);
            *(float2*)(Cb + (size_t)(row0 + 8) * ldc + col) = make_float2(c2, c3);
        }
    }
}

// ---------------- flash attention with soft cap + sliding window ----------------
#define ST 16
__global__ __launch_bounds__(256)
void attn_kernel(const float* __restrict__ q, const float* __restrict__ k,
                 const float* __restrict__ v, float* __restrict__ out, int isLocal)
{
    __shared__ float ks[ST][HDIM];
    __shared__ float vs[ST][HDIM];
    int b = blockIdx.z, n = blockIdx.y;
    int t0 = blockIdx.x * 16;
    int kh = n >> 1;                       // GQA: group size 2
    int tid = threadIdx.x, wid = tid >> 5, lane = tid & 31;
    int tq = t0 + wid * 2;

    float qr[2][8];
#pragma unroll
    for (int qi = 0; qi < 2; qi++) {
        const float* qp = q + (((size_t)(b * SEQ + tq + qi) * NHEADS + n) * HDIM) + lane * 8;
        float4 a = *(const float4*)qp;
        float4 b4 = *(const float4*)(qp + 4);
        qr[qi][0] = a.x;  qr[qi][1] = a.y;  qr[qi][2] = a.z;  qr[qi][3] = a.w;
        qr[qi][4] = b4.x; qr[qi][5] = b4.y; qr[qi][6] = b4.z; qr[qi][7] = b4.w;
    }
    float m[2] = {-INFINITY, -INFINITY};
    float lsum[2] = {0.f, 0.f};
    float acc[2][8];
#pragma unroll
    for (int qi = 0; qi < 2; qi++)
#pragma unroll
        for (int j = 0; j < 8; j++) acc[qi][j] = 0.f;

    int sEnd = t0 + 15;
    int sLo = 0;
    if (isLocal) { sLo = t0 - (WINDOW_SZ - 1); if (sLo < 0) sLo = 0; }
    sLo &= ~(ST - 1);

    int lr = tid >> 4, lc = tid & 15;
    for (int sB = sLo; sB <= sEnd; sB += ST) {
        const float* kp = k + ((size_t)(b * SEQ + sB + lr) * KVHEADS + kh) * HDIM;
        const float* vp = v + ((size_t)(b * SEQ + sB + lr) * KVHEADS + kh) * HDIM;
#pragma unroll
        for (int j = 0; j < 4; j++) {
            int c = (lc + j * 16) * 4;
            *(float4*)&ks[lr][c] = *(const float4*)(kp + c);
            *(float4*)&vs[lr][c] = *(const float4*)(vp + c);
        }
        __syncthreads();
#pragma unroll 4
        for (int ss = 0; ss < ST; ss++) {
            int s = sB + ss;
            float kk[8];
            *(float4*)&kk[0] = *(float4*)&ks[ss][lane * 8];
            *(float4*)&kk[4] = *(float4*)&ks[ss][lane * 8 + 4];
            float d0 = 0.f, d1 = 0.f;
#pragma unroll
            for (int j = 0; j < 8; j++) { d0 += qr[0][j] * kk[j]; d1 += qr[1][j] * kk[j]; }
#pragma unroll
            for (int o = 16; o; o >>= 1) {
                d0 += __shfl_xor_sync(0xffffffffu, d0, o);
                d1 += __shfl_xor_sync(0xffffffffu, d1, o);
            }
            float vv[8];
            *(float4*)&vv[0] = *(float4*)&vs[ss][lane * 8];
            *(float4*)&vv[4] = *(float4*)&vs[ss][lane * 8 + 4];
#pragma unroll
            for (int qi = 0; qi < 2; qi++) {
                int t = tq + qi;
                bool valid = (s <= t) && (!isLocal || (t - s) < WINDOW_SZ);
                if (valid) {
                    float dd = qi ? d1 : d0;
                    float lg = ATTN_CAP * tanhf(dd / ATTN_CAP);
                    float mn = fmaxf(m[qi], lg);
                    float corr = expf(m[qi] - mn);
                    float p = expf(lg - mn);
                    lsum[qi] = lsum[qi] * corr + p;
#pragma unroll
                    for (int j = 0; j < 8; j++) acc[qi][j] = acc[qi][j] * corr + p * vv[j];
                    m[qi] = mn;
                }
            }
        }
        __syncthreads();
    }
#pragma unroll
    for (int qi = 0; qi < 2; qi++) {
        float inv = 1.f / lsum[qi];
        float* op = out + (((size_t)(b * SEQ + tq + qi) * NHEADS + n) * HDIM) + lane * 8;
        float o0[4] = {acc[qi][0]*inv, acc[qi][1]*inv, acc[qi][2]*inv, acc[qi][3]*inv};
        float o1[4] = {acc[qi][4]*inv, acc[qi][5]*inv, acc[qi][6]*inv, acc[qi][7]*inv};
        *(float4*)op       = make_float4(o0[0], o0[1], o0[2], o0[3]);
        *(float4*)(op + 4) = make_float4(o1[0], o1[1], o1[2], o1[3]);
    }
}

// ---------------- host launcher ----------------
extern "C" void kernel_launch(void* const* d_in, const int* in_sizes, int n_in,
                              void* d_out, int out_size)
{
    const int*   tokens    = (const int*)  d_in[0];
    const float* emb       = (const float*)d_in[1];
    const float* w_q       = (const float*)d_in[2];
    const float* w_kv      = (const float*)d_in[3];
    const float* w_o       = (const float*)d_in[4];
    const float* attn_nrm  = (const float*)d_in[5];
    const float* pattn_nrm = (const float*)d_in[6];
    const float* ffw_nrm   = (const float*)d_in[7];
    const float* pffw_nrm  = (const float*)d_in[8];
    const float* q_nrm     = (const float*)d_in[9];
    const float* k_nrm     = (const float*)d_in[10];
    const float* gate_w    = (const float*)d_in[11];
    const float* down_w    = (const float*)d_in[12];
    const float* final_nrm = (const float*)d_in[13];
    float* out = (float*)d_out;

    float *x, *h, *q, *k, *v, *ao, *gate, *up;
    cudaGetSymbolAddress((void**)&x,    g_x);
    cudaGetSymbolAddress((void**)&h,    g_h);
    cudaGetSymbolAddress((void**)&q,    g_q);
    cudaGetSymbolAddress((void**)&k,    g_k);
    cudaGetSymbolAddress((void**)&v,    g_v);
    cudaGetSymbolAddress((void**)&ao,   g_ao);
    cudaGetSymbolAddress((void**)&gate, g_gate);
    cudaGetSymbolAddress((void**)&up,   g_up);

    // embedding
    {
        long total = (long)MROWS * DMODEL;
        embed_kernel<<<(unsigned)((total + 255) / 256), 256>>>(tokens, emb, x, total);
    }

    for (int l = 0; l < LAYERS; l++) {
        int   isLocal = (l % 2 == 0);
        float base    = isLocal ? 10000.f : 1000000.f;
        float posDiv  = isLocal ? 1.f : 8.f;

        // attn pre-norm
        rmsnorm_kernel<<<MROWS, 256>>>(x, h, attn_nrm + (size_t)l * DMODEL, DMODEL);

        // q projection: 8 batched GEMMs [4096,2304]x[2304,256]
        {
            dim3 grid(HDIM / 128, MROWS / 128, NHEADS);
            tgemm_kernel<<<grid, 256>>>(h, DMODEL, 0,
                w_q + (size_t)l * NHEADS * DMODEL * HDIM, HDIM, (long)DMODEL * HDIM,
                q, NHEADS * HDIM, HDIM, DMODEL, 0, 0);
        }
        // k / v projections
        {
            dim3 grid(HDIM / 128, MROWS / 128, KVHEADS);
            tgemm_kernel<<<grid, 256>>>(h, DMODEL, 0,
                w_kv + (size_t)(l * 2 + 0) * KVHEADS * DMODEL * HDIM, HDIM, (long)DMODEL * HDIM,
                k, KVHEADS * HDIM, HDIM, DMODEL, 0, 0);
            tgemm_kernel<<<grid, 256>>>(h, DMODEL, 0,
                w_kv + (size_t)(l * 2 + 1) * KVHEADS * DMODEL * HDIM, HDIM, (long)DMODEL * HDIM,
                v, KVHEADS * HDIM, HDIM, DMODEL, 0, 0);
        }
        // qk-norm
        rmsnorm_kernel<<<MROWS * NHEADS, 256>>>(q, q, q_nrm + (size_t)l * HDIM, HDIM);
        rmsnorm_kernel<<<MROWS * KVHEADS, 256>>>(k, k, k_nrm + (size_t)l * HDIM, HDIM);
        // rope (+ H^-0.5 scale on q)
        {
            long tq = (long)MROWS * NHEADS * (HDIM / 2);
            long tk = (long)MROWS * KVHEADS * (HDIM / 2);
            rope_kernel<<<(unsigned)((tq + 255) / 256), 256>>>(q, NHEADS,  base, posDiv, 0.0625f, tq);
            rope_kernel<<<(unsigned)((tk + 255) / 256), 256>>>(k, KVHEADS, base, posDiv, 1.0f,    tk);
        }
        // attention
        {
            dim3 grid(SEQ / 16, NHEADS, BATCH);
            attn_kernel<<<grid, 256>>>(q, k, v, ao, isLocal);
        }
        // output projection
        {
            dim3 grid(DMODEL / 128, MROWS / 128, 1);
            tgemm_kernel<<<grid, 256>>>(ao, NHEADS * HDIM, 0,
                w_o + (size_t)l * NHEADS * HDIM * DMODEL, DMODEL, 0,
                h, DMODEL, 0, NHEADS * HDIM, 0, 0);
        }
        add_rmsnorm_kernel<<<MROWS, 256>>>(x, h, pattn_nrm + (size_t)l * DMODEL, DMODEL);

        // MLP
        rmsnorm_kernel<<<MROWS, 256>>>(x, h, ffw_nrm + (size_t)l * DMODEL, DMODEL);
        {
            dim3 grid(FFN / 128, MROWS / 128, 1);
            tgemm_kernel<<<grid, 256>>>(h, DMODEL, 0,
                gate_w + (size_t)(l * 2 + 0) * DMODEL * FFN, FFN, 0,
                gate, FFN, 0, DMODEL, 0, 0);
            tgemm_kernel<<<grid, 256>>>(h, DMODEL, 0,
                gate_w + (size_t)(l * 2 + 1) * DMODEL * FFN, FFN, 0,
                up, FFN, 0, DMODEL, 0, 0);
        }
        {
            long total = (long)MROWS * FFN;
            geglu_kernel<<<(unsigned)((total + 255) / 256), 256>>>(gate, up, total);
        }
        {
            dim3 grid(DMODEL / 128, MROWS / 128, 1);
            tgemm_kernel<<<grid, 256>>>(gate, FFN, 0,
                down_w + (size_t)l * FFN * DMODEL, DMODEL, 0,
                h, DMODEL, 0, FFN, 0, 0);
        }
        add_rmsnorm_kernel<<<MROWS, 256>>>(x, h, pffw_nrm + (size_t)l * DMODEL, DMODEL);
    }

    // final norm + tied-embedding decode with soft cap
    rmsnorm_kernel<<<MROWS, 256>>>(x, h, final_nrm, DMODEL);
    {
        dim3 grid(VOCAB / 128, MROWS / 128, 1);
        tgemm_kernel<<<grid, 256>>>(h, DMODEL, 0,
            emb, DMODEL, 0,
            out, VOCAB, 0, DMODEL, 1, 1);
    }
}

// round 7
// speedup vs baseline: 3.2170x; 1.4886x over previous
#include <cuda_runtime.h>
#include <cuda_fp16.h>
#include <math.h>
#include <stdint.h>

// ---------------- problem dims ----------------
#define LAYERS   4
#define VOCAB    32000
#define DMODEL   2304
#define FFN      9216
#define NHEADS   8
#define KVHEADS  4
#define HDIM     256
#define BATCH    2
#define SEQ      2048
#define MROWS    (BATCH*SEQ)      // 4096
#define WINDOW_SZ 1024
#define ATTN_CAP 50.0f
#define FINAL_CAP 30.0f

// ---------------- static scratch (no allocations allowed) ----------------
__device__ float g_x   [MROWS*DMODEL];
__device__ float g_h   [MROWS*DMODEL];
__device__ float g_q   [MROWS*NHEADS*HDIM];
__device__ float g_k   [MROWS*KVHEADS*HDIM];
__device__ float g_v   [MROWS*KVHEADS*HDIM];
__device__ float g_ao  [MROWS*NHEADS*HDIM];
__device__ float g_gate[MROWS*FFN];
__device__ float g_up  [MROWS*FFN];
__device__ float2 g_ropetab[2][SEQ][HDIM/2];

// ---------------- helpers ----------------
__device__ __forceinline__ float block_reduce_sum(float v) {
    __shared__ float sh[8];
    int lane = threadIdx.x & 31, wid = threadIdx.x >> 5;
#pragma unroll
    for (int o = 16; o; o >>= 1) v += __shfl_xor_sync(0xffffffffu, v, o);
    if (lane == 0) sh[wid] = v;
    __syncthreads();
    if (wid == 0) {
        float w = (lane < 8) ? sh[lane] : 0.f;
#pragma unroll
        for (int o = 4; o; o >>= 1) w += __shfl_xor_sync(0xffffffffu, w, o);
        if (lane == 0) sh[0] = w;
    }
    __syncthreads();
    return sh[0];
}

__device__ __forceinline__ float fast_tanh(float x) {
    float t = fminf(fmaxf(x, -20.f), 20.f);
    float e = __expf(2.f * t);
    return __fdividef(e - 1.f, e + 1.f);
}

__device__ __forceinline__ uint32_t packh(half lo, half hi) {
    half2 h = __halves2half2(lo, hi);
    return *(uint32_t*)&h;
}

// ---------------- embedding ----------------
__global__ void embed_kernel(const int* __restrict__ tokens,
                             const float* __restrict__ emb,
                             float* __restrict__ x, long total) {
    long idx = (long)blockIdx.x * blockDim.x + threadIdx.x;
    if (idx >= total) return;
    long row = idx / DMODEL;
    long d   = idx % DMODEL;
    int tok  = tokens[row];
    x[idx] = emb[(size_t)tok * DMODEL + d] * 48.0f;   // sqrt(2304)=48 exact
}

// ---------------- rmsnorm ----------------
__global__ void rmsnorm_kernel(const float* __restrict__ in, float* __restrict__ out,
                               const float* __restrict__ w, int cols) {
    long row = blockIdx.x;
    const float* ip = in + row * cols;
    float* op = out + row * cols;
    float s = 0.f;
    for (int i = threadIdx.x; i < cols; i += blockDim.x) { float v = ip[i]; s += v * v; }
    float tot = block_reduce_sum(s);
    float r = rsqrtf(tot / (float)cols + 1e-6f);
    for (int i = threadIdx.x; i < cols; i += blockDim.x)
        op[i] = ip[i] * r * (1.f + w[i]);
}

// ---------------- x += rmsnorm(h, w) ----------------
__global__ void add_rmsnorm_kernel(float* __restrict__ x, const float* __restrict__ h,
                                   const float* __restrict__ w, int cols) {
    long row = blockIdx.x;
    const float* hp = h + row * cols;
    float* xp = x + row * cols;
    float s = 0.f;
    for (int i = threadIdx.x; i < cols; i += blockDim.x) { float v = hp[i]; s += v * v; }
    float tot = block_reduce_sum(s);
    float r = rsqrtf(tot / (float)cols + 1e-6f);
    for (int i = threadIdx.x; i < cols; i += blockDim.x)
        xp[i] += hp[i] * r * (1.f + w[i]);
}

// ---------------- RoPE table (computed once per launch, double precision) ----------------
__global__ void rope_table_kernel() {
    int idx = blockIdx.x * blockDim.x + threadIdx.x;   // 2*2048*128 total
    int mode = idx >> 18;                              // 2048*128 = 2^18
    int rem  = idx & 262143;
    int t = rem >> 7, i = rem & 127;
    double base = mode ? 1000000.0 : 10000.0;
    double dv   = mode ? 8.0 : 1.0;
    double frac = (2.0 * (double)i) / (double)HDIM;
    double ts   = exp(frac * log(base));
    double ang  = ((double)t / dv) / ts;
    g_ropetab[mode][t][i] = make_float2((float)sin(ang), (float)cos(ang));
}

__global__ void rope_apply_kernel(float* __restrict__ x, int nh, int mode,
                                  float mul, long total) {
    long idx = (long)blockIdx.x * blockDim.x + threadIdx.x;
    if (idx >= total) return;                       // total = rows * (HDIM/2)
    int i    = (int)(idx & (HDIM/2 - 1));
    long row = idx >> 7;
    int t = (int)((row / nh) % SEQ);
    float2 sc = g_ropetab[mode][t][i];
    float sv = sc.x, cv = sc.y;
    float* p = x + (size_t)row * HDIM;
    float x1 = p[i], x2 = p[i + HDIM/2];
    p[i]          = (x1 * cv - x2 * sv) * mul;
    p[i + HDIM/2] = (x2 * cv + x1 * sv) * mul;
}

// ---------------- GeGLU ----------------
__global__ void geglu_kernel(float* __restrict__ gate, const float* __restrict__ up, long total) {
    long idx = (long)blockIdx.x * blockDim.x + threadIdx.x;
    if (idx >= total) return;
    float x = gate[idx];
    float x3 = x * x * x;
    float tn = fast_tanh(0.7978845608028654f * (x + 0.044715f * x3));
    gate[idx] = 0.5f * x * (1.f + tn) * up[idx];
}

// ================= FP16 tensor-core GEMM (m16n8k16, fp32 accum) =================
// C = A(MxK fp32 row-major) * B ; transB=0: B row-major [K,N] ; transB=1: B [N,K] (C=A*B^T)
// 128x128x16 CTA tile, 256 threads, warps 2(M) x 4(N), warp tile 64x32.
// A / B(transB) staged as half [row][k] with 24-half rows (48 B: fragment banks 12g+t4
// cover all 32 -> conflict-free). B(!transB) staged k-major [16][136] halves.
__device__ __forceinline__ void mma_f16(float& c0, float& c1, float& c2, float& c3,
                                        uint32_t a0, uint32_t a1, uint32_t a2, uint32_t a3,
                                        uint32_t b0, uint32_t b1) {
    asm volatile(
        "mma.sync.aligned.m16n8k16.row.col.f32.f16.f16.f32 "
        "{%0,%1,%2,%3}, {%4,%5,%6,%7}, {%8,%9}, {%0,%1,%2,%3};\n"
        : "+f"(c0), "+f"(c1), "+f"(c2), "+f"(c3)
        : "r"(a0), "r"(a1), "r"(a2), "r"(a3), "r"(b0), "r"(b1));
}

__global__ __launch_bounds__(256)
void hgemm_kernel(const float* __restrict__ A, int lda, long sA,
                  const float* __restrict__ B, int ldb, long sB,
                  float* __restrict__ C, int ldc, long sC,
                  int Kd, int transB, int capMode)
{
    __shared__ half As [2][128][24];
    __shared__ half Bnk[2][128][24];
    __shared__ half Bkn[2][16][136];

    const float* Ab = A + (long)blockIdx.z * sA;
    const float* Bb = B + (long)blockIdx.z * sB;
    float*       Cb = C + (long)blockIdx.z * sC;
    const int m0 = blockIdx.y * 128;
    const int n0 = blockIdx.x * 128;
    const int tid = threadIdx.x;
    const int wid = tid >> 5, lane = tid & 31;
    const int g = lane >> 2, t4 = lane & 3;
    const int wm = (wid & 1) * 64;
    const int wn = (wid >> 1) * 32;

    const int arow = tid >> 2, ak = (tid & 3) * 4;   // A / B-nk staging map
    const int bkr  = tid >> 4, bnc = (tid & 15) * 4; // B-kn staging map

    float acc[4][4][4];
#pragma unroll
    for (int i = 0; i < 4; i++)
#pragma unroll
        for (int j = 0; j < 4; j++)
#pragma unroll
            for (int r = 0; r < 4; r++) acc[i][j][r] = 0.f;

    // ---- prologue: stage tile 0 into buffer 0 ----
    {
        float4 av0 = *(const float4*)(Ab + (size_t)(m0 + arow) * lda + ak);
        float4 av1 = *(const float4*)(Ab + (size_t)(m0 + arow + 64) * lda + ak);
        *(half2*)&As[0][arow][ak]          = __floats2half2_rn(av0.x, av0.y);
        *(half2*)&As[0][arow][ak + 2]      = __floats2half2_rn(av0.z, av0.w);
        *(half2*)&As[0][arow + 64][ak]     = __floats2half2_rn(av1.x, av1.y);
        *(half2*)&As[0][arow + 64][ak + 2] = __floats2half2_rn(av1.z, av1.w);
        if (transB) {
            float4 bv0 = *(const float4*)(Bb + (size_t)(n0 + arow) * ldb + ak);
            float4 bv1 = *(const float4*)(Bb + (size_t)(n0 + arow + 64) * ldb + ak);
            *(half2*)&Bnk[0][arow][ak]          = __floats2half2_rn(bv0.x, bv0.y);
            *(half2*)&Bnk[0][arow][ak + 2]      = __floats2half2_rn(bv0.z, bv0.w);
            *(half2*)&Bnk[0][arow + 64][ak]     = __floats2half2_rn(bv1.x, bv1.y);
            *(half2*)&Bnk[0][arow + 64][ak + 2] = __floats2half2_rn(bv1.z, bv1.w);
        } else {
            float4 bv0 = *(const float4*)(Bb + (size_t)bkr * ldb + n0 + bnc);
            float4 bv1 = *(const float4*)(Bb + (size_t)bkr * ldb + n0 + bnc + 64);
            *(half2*)&Bkn[0][bkr][bnc]      = __floats2half2_rn(bv0.x, bv0.y);
            *(half2*)&Bkn[0][bkr][bnc + 2]  = __floats2half2_rn(bv0.z, bv0.w);
            *(half2*)&Bkn[0][bkr][bnc + 64] = __floats2half2_rn(bv1.x, bv1.y);
            *(half2*)&Bkn[0][bkr][bnc + 66] = __floats2half2_rn(bv1.z, bv1.w);
        }
    }
    __syncthreads();

    int buf = 0;
    for (int k0 = 0; k0 < Kd; k0 += 16) {
        const bool hasNext = (k0 + 16) < Kd;
        float4 pa0, pa1, pb0, pb1;
        if (hasNext) {
            int kn = k0 + 16;
            pa0 = *(const float4*)(Ab + (size_t)(m0 + arow) * lda + kn + ak);
            pa1 = *(const float4*)(Ab + (size_t)(m0 + arow + 64) * lda + kn + ak);
            if (transB) {
                pb0 = *(const float4*)(Bb + (size_t)(n0 + arow) * ldb + kn + ak);
                pb1 = *(const float4*)(Bb + (size_t)(n0 + arow + 64) * ldb + kn + ak);
            } else {
                pb0 = *(const float4*)(Bb + (size_t)(kn + bkr) * ldb + n0 + bnc);
                pb1 = *(const float4*)(Bb + (size_t)(kn + bkr) * ldb + n0 + bnc + 64);
            }
        }

        // ---- compute on current buffer: one k16 step, 16 MMAs ----
        {
            uint32_t afr[4][4];
            uint32_t bfr[4][2];
#pragma unroll
            for (int i = 0; i < 4; i++) {
                const int r = wm + i * 16 + g;
                afr[i][0] = *(const uint32_t*)&As[buf][r][2 * t4];
                afr[i][1] = *(const uint32_t*)&As[buf][r + 8][2 * t4];
                afr[i][2] = *(const uint32_t*)&As[buf][r][2 * t4 + 8];
                afr[i][3] = *(const uint32_t*)&As[buf][r + 8][2 * t4 + 8];
            }
            if (transB) {
#pragma unroll
                for (int j = 0; j < 4; j++) {
                    const int n = wn + j * 8 + g;
                    bfr[j][0] = *(const uint32_t*)&Bnk[buf][n][2 * t4];
                    bfr[j][1] = *(const uint32_t*)&Bnk[buf][n][2 * t4 + 8];
                }
            } else {
#pragma unroll
                for (int j = 0; j < 4; j++) {
                    const int n = wn + j * 8 + g;
                    bfr[j][0] = packh(Bkn[buf][2 * t4][n],     Bkn[buf][2 * t4 + 1][n]);
                    bfr[j][1] = packh(Bkn[buf][2 * t4 + 8][n], Bkn[buf][2 * t4 + 9][n]);
                }
            }
#pragma unroll
            for (int i = 0; i < 4; i++)
#pragma unroll
                for (int j = 0; j < 4; j++)
                    mma_f16(acc[i][j][0], acc[i][j][1], acc[i][j][2], acc[i][j][3],
                            afr[i][0], afr[i][1], afr[i][2], afr[i][3],
                            bfr[j][0], bfr[j][1]);
        }

        if (hasNext) {
            int nb = buf ^ 1;
            *(half2*)&As[nb][arow][ak]          = __floats2half2_rn(pa0.x, pa0.y);
            *(half2*)&As[nb][arow][ak + 2]      = __floats2half2_rn(pa0.z, pa0.w);
            *(half2*)&As[nb][arow + 64][ak]     = __floats2half2_rn(pa1.x, pa1.y);
            *(half2*)&As[nb][arow + 64][ak + 2] = __floats2half2_rn(pa1.z, pa1.w);
            if (transB) {
                *(half2*)&Bnk[nb][arow][ak]          = __floats2half2_rn(pb0.x, pb0.y);
                *(half2*)&Bnk[nb][arow][ak + 2]      = __floats2half2_rn(pb0.z, pb0.w);
                *(half2*)&Bnk[nb][arow + 64][ak]     = __floats2half2_rn(pb1.x, pb1.y);
                *(half2*)&Bnk[nb][arow + 64][ak + 2] = __floats2half2_rn(pb1.z, pb1.w);
            } else {
                *(half2*)&Bkn[nb][bkr][bnc]      = __floats2half2_rn(pb0.x, pb0.y);
                *(half2*)&Bkn[nb][bkr][bnc + 2]  = __floats2half2_rn(pb0.z, pb0.w);
                *(half2*)&Bkn[nb][bkr][bnc + 64] = __floats2half2_rn(pb1.x, pb1.y);
                *(half2*)&Bkn[nb][bkr][bnc + 66] = __floats2half2_rn(pb1.z, pb1.w);
            }
        }
        __syncthreads();
        buf ^= 1;
    }

    // ---- epilogue ----
#pragma unroll
    for (int i = 0; i < 4; i++) {
#pragma unroll
        for (int j = 0; j < 4; j++) {
            int row0 = m0 + wm + i * 16 + g;
            int col  = n0 + wn + j * 8 + 2 * t4;
            float c0 = acc[i][j][0], c1 = acc[i][j][1];
            float c2 = acc[i][j][2], c3 = acc[i][j][3];
            if (capMode) {
                c0 = FINAL_CAP * fast_tanh(c0 * (1.f / FINAL_CAP));
                c1 = FINAL_CAP * fast_tanh(c1 * (1.f / FINAL_CAP));
                c2 = FINAL_CAP * fast_tanh(c2 * (1.f / FINAL_CAP));
                c3 = FINAL_CAP * fast_tanh(c3 * (1.f / FINAL_CAP));
            }
            *(float2*)(Cb + (size_t)row0 * ldc + col)       = make_float2(c0, c1);
            *(float2*)(Cb + (size_t)(row0 + 8) * ldc + col) = make_float2(c2, c3);
        }
    }
}

// ---------------- flash attention with soft cap + sliding window ----------------
#define ST 16
__global__ __launch_bounds__(256)
void attn_kernel(const float* __restrict__ q, const float* __restrict__ k,
                 const float* __restrict__ v, float* __restrict__ out, int isLocal)
{
    __shared__ float ks[ST][HDIM];
    __shared__ float vs[ST][HDIM];
    int b = blockIdx.z, n = blockIdx.y;
    int t0 = blockIdx.x * 16;
    int kh = n >> 1;                       // GQA: group size 2
    int tid = threadIdx.x, wid = tid >> 5, lane = tid & 31;
    int tq = t0 + wid * 2;

    float qr[2][8];
#pragma unroll
    for (int qi = 0; qi < 2; qi++) {
        const float* qp = q + (((size_t)(b * SEQ + tq + qi) * NHEADS + n) * HDIM) + lane * 8;
        float4 a = *(const float4*)qp;
        float4 b4 = *(const float4*)(qp + 4);
        qr[qi][0] = a.x;  qr[qi][1] = a.y;  qr[qi][2] = a.z;  qr[qi][3] = a.w;
        qr[qi][4] = b4.x; qr[qi][5] = b4.y; qr[qi][6] = b4.z; qr[qi][7] = b4.w;
    }
    float m[2] = {-1e30f, -1e30f};
    float lsum[2] = {0.f, 0.f};
    float acc[2][8];
#pragma unroll
    for (int qi = 0; qi < 2; qi++)
#pragma unroll
        for (int j = 0; j < 8; j++) acc[qi][j] = 0.f;

    int sEnd = t0 + 15;
    int sLo = 0;
    if (isLocal) { sLo = t0 - (WINDOW_SZ - 1); if (sLo < 0) sLo = 0; }
    sLo &= ~(ST - 1);

    int lr = tid >> 4, lc = tid & 15;
    for (int sB = sLo; sB <= sEnd; sB += ST) {
        const float* kp = k + ((size_t)(b * SEQ + sB + lr) * KVHEADS + kh) * HDIM;
        const float* vp = v + ((size_t)(b * SEQ + sB + lr) * KVHEADS + kh) * HDIM;
#pragma unroll
        for (int j = 0; j < 4; j++) {
            int c = (lc + j * 16) * 4;
            *(float4*)&ks[lr][c] = *(const float4*)(kp + c);
            *(float4*)&vs[lr][c] = *(const float4*)(vp + c);
        }
        __syncthreads();
#pragma unroll 4
        for (int ss = 0; ss < ST; ss++) {
            int s = sB + ss;
            float kk[8];
            *(float4*)&kk[0] = *(float4*)&ks[ss][lane * 8];
            *(float4*)&kk[4] = *(float4*)&ks[ss][lane * 8 + 4];
            float d0 = 0.f, d1 = 0.f;
#pragma unroll
            for (int j = 0; j < 8; j++) { d0 += qr[0][j] * kk[j]; d1 += qr[1][j] * kk[j]; }
#pragma unroll
            for (int o = 16; o; o >>= 1) {
                d0 += __shfl_xor_sync(0xffffffffu, d0, o);
                d1 += __shfl_xor_sync(0xffffffffu, d1, o);
            }
            float vv[8];
            *(float4*)&vv[0] = *(float4*)&vs[ss][lane * 8];
            *(float4*)&vv[4] = *(float4*)&vs[ss][lane * 8 + 4];
#pragma unroll
            for (int qi = 0; qi < 2; qi++) {
                int t = tq + qi;
                bool valid = (s <= t) && (!isLocal || (t - s) < WINDOW_SZ);
                if (valid) {
                    float dd = qi ? d1 : d0;
                    float lg = ATTN_CAP * fast_tanh(dd * (1.f / ATTN_CAP));
                    if (lg > m[qi]) {      // warp-uniform (dd uniform after butterfly)
                        float corr = __expf(m[qi] - lg);
                        m[qi] = lg;
                        lsum[qi] *= corr;
#pragma unroll
                        for (int j = 0; j < 8; j++) acc[qi][j] *= corr;
                    }
                    float p = __expf(lg - m[qi]);
                    lsum[qi] += p;
#pragma unroll
                    for (int j = 0; j < 8; j++) acc[qi][j] += p * vv[j];
                }
            }
        }
        __syncthreads();
    }
#pragma unroll
    for (int qi = 0; qi < 2; qi++) {
        float inv = 1.f / lsum[qi];
        float* op = out + (((size_t)(b * SEQ + tq + qi) * NHEADS + n) * HDIM) + lane * 8;
        *(float4*)op       = make_float4(acc[qi][0]*inv, acc[qi][1]*inv, acc[qi][2]*inv, acc[qi][3]*inv);
        *(float4*)(op + 4) = make_float4(acc[qi][4]*inv, acc[qi][5]*inv, acc[qi][6]*inv, acc[qi][7]*inv);
    }
}

// ---------------- host launcher ----------------
extern "C" void kernel_launch(void* const* d_in, const int* in_sizes, int n_in,
                              void* d_out, int out_size)
{
    const int*   tokens    = (const int*)  d_in[0];
    const float* emb       = (const float*)d_in[1];
    const float* w_q       = (const float*)d_in[2];
    const float* w_kv      = (const float*)d_in[3];
    const float* w_o       = (const float*)d_in[4];
    const float* attn_nrm  = (const float*)d_in[5];
    const float* pattn_nrm = (const float*)d_in[6];
    const float* ffw_nrm   = (const float*)d_in[7];
    const float* pffw_nrm  = (const float*)d_in[8];
    const float* q_nrm     = (const float*)d_in[9];
    const float* k_nrm     = (const float*)d_in[10];
    const float* gate_w    = (const float*)d_in[11];
    const float* down_w    = (const float*)d_in[12];
    const float* final_nrm = (const float*)d_in[13];
    float* out = (float*)d_out;

    float *x, *h, *q, *k, *v, *ao, *gate, *up;
    cudaGetSymbolAddress((void**)&x,    g_x);
    cudaGetSymbolAddress((void**)&h,    g_h);
    cudaGetSymbolAddress((void**)&q,    g_q);
    cudaGetSymbolAddress((void**)&k,    g_k);
    cudaGetSymbolAddress((void**)&v,    g_v);
    cudaGetSymbolAddress((void**)&ao,   g_ao);
    cudaGetSymbolAddress((void**)&gate, g_gate);
    cudaGetSymbolAddress((void**)&up,   g_up);

    // RoPE table (deterministic; recomputed each launch)
    rope_table_kernel<<<2 * SEQ * (HDIM/2) / 256, 256>>>();

    // embedding
    {
        long total = (long)MROWS * DMODEL;
        embed_kernel<<<(unsigned)((total + 255) / 256), 256>>>(tokens, emb, x, total);
    }

    for (int l = 0; l < LAYERS; l++) {
        int isLocal = (l % 2 == 0);
        int mode    = isLocal ? 0 : 1;

        // attn pre-norm
        rmsnorm_kernel<<<MROWS, 256>>>(x, h, attn_nrm + (size_t)l * DMODEL, DMODEL);

        // q projection: 8 batched GEMMs [4096,2304]x[2304,256]
        {
            dim3 grid(HDIM / 128, MROWS / 128, NHEADS);
            hgemm_kernel<<<grid, 256>>>(h, DMODEL, 0,
                w_q + (size_t)l * NHEADS * DMODEL * HDIM, HDIM, (long)DMODEL * HDIM,
                q, NHEADS * HDIM, HDIM, DMODEL, 0, 0);
        }
        // k / v projections
        {
            dim3 grid(HDIM / 128, MROWS / 128, KVHEADS);
            hgemm_kernel<<<grid, 256>>>(h, DMODEL, 0,
                w_kv + (size_t)(l * 2 + 0) * KVHEADS * DMODEL * HDIM, HDIM, (long)DMODEL * HDIM,
                k, KVHEADS * HDIM, HDIM, DMODEL, 0, 0);
            hgemm_kernel<<<grid, 256>>>(h, DMODEL, 0,
                w_kv + (size_t)(l * 2 + 1) * KVHEADS * DMODEL * HDIM, HDIM, (long)DMODEL * HDIM,
                v, KVHEADS * HDIM, HDIM, DMODEL, 0, 0);
        }
        // qk-norm
        rmsnorm_kernel<<<MROWS * NHEADS, 256>>>(q, q, q_nrm + (size_t)l * HDIM, HDIM);
        rmsnorm_kernel<<<MROWS * KVHEADS, 256>>>(k, k, k_nrm + (size_t)l * HDIM, HDIM);
        // rope (+ H^-0.5 scale on q)
        {
            long tq = (long)MROWS * NHEADS * (HDIM / 2);
            long tk = (long)MROWS * KVHEADS * (HDIM / 2);
            rope_apply_kernel<<<(unsigned)((tq + 255) / 256), 256>>>(q, NHEADS,  mode, 0.0625f, tq);
            rope_apply_kernel<<<(unsigned)((tk + 255) / 256), 256>>>(k, KVHEADS, mode, 1.0f,    tk);
        }
        // attention
        {
            dim3 grid(SEQ / 16, NHEADS, BATCH);
            attn_kernel<<<grid, 256>>>(q, k, v, ao, isLocal);
        }
        // output projection
        {
            dim3 grid(DMODEL / 128, MROWS / 128, 1);
            hgemm_kernel<<<grid, 256>>>(ao, NHEADS * HDIM, 0,
                w_o + (size_t)l * NHEADS * HDIM * DMODEL, DMODEL, 0,
                h, DMODEL, 0, NHEADS * HDIM, 0, 0);
        }
        add_rmsnorm_kernel<<<MROWS, 256>>>(x, h, pattn_nrm + (size_t)l * DMODEL, DMODEL);

        // MLP
        rmsnorm_kernel<<<MROWS, 256>>>(x, h, ffw_nrm + (size_t)l * DMODEL, DMODEL);
        {
            dim3 grid(FFN / 128, MROWS / 128, 1);
            hgemm_kernel<<<grid, 256>>>(h, DMODEL, 0,
                gate_w + (size_t)(l * 2 + 0) * DMODEL * FFN, FFN, 0,
                gate, FFN, 0, DMODEL, 0, 0);
            hgemm_kernel<<<grid, 256>>>(h, DMODEL, 0,
                gate_w + (size_t)(l * 2 + 1) * DMODEL * FFN, FFN, 0,
                up, FFN, 0, DMODEL, 0, 0);
        }
        {
            long total = (long)MROWS * FFN;
            geglu_kernel<<<(unsigned)((total + 255) / 256), 256>>>(gate, up, total);
        }
        {
            dim3 grid(DMODEL / 128, MROWS / 128, 1);
            hgemm_kernel<<<grid, 256>>>(gate, FFN, 0,
                down_w + (size_t)l * FFN * DMODEL, DMODEL, 0,
                h, DMODEL, 0, FFN, 0, 0);
        }
        add_rmsnorm_kernel<<<MROWS, 256>>>(x, h, pffw_nrm + (size_t)l * DMODEL, DMODEL);
    }

    // final norm + tied-embedding decode with soft cap
    rmsnorm_kernel<<<MROWS, 256>>>(x, h, final_nrm, DMODEL);
    {
        dim3 grid(VOCAB / 128, MROWS / 128, 1);
        hgemm_kernel<<<grid, 256>>>(h, DMODEL, 0,
            emb, DMODEL, 0,
            out, VOCAB, 0, DMODEL, 1, 1);
    }
}

// round 8
// speedup vs baseline: 3.4910x; 1.0852x over previous
#include <cuda_runtime.h>
#include <cuda_fp16.h>
#include <math.h>
#include <stdint.h>

// ---------------- problem dims ----------------
#define LAYERS   4
#define VOCAB    32000
#define DMODEL   2304
#define FFN      9216
#define NHEADS   8
#define KVHEADS  4
#define HDIM     256
#define BATCH    2
#define SEQ      2048
#define MROWS    (BATCH*SEQ)      // 4096
#define WINDOW_SZ 1024
#define ATTN_CAP 50.0f
#define FINAL_CAP 30.0f

// ---------------- static scratch (no allocations allowed) ----------------
__device__ float g_x   [MROWS*DMODEL];
__device__ float g_h   [MROWS*DMODEL];
__device__ float g_q   [MROWS*NHEADS*HDIM];
__device__ float g_k   [MROWS*KVHEADS*HDIM];
__device__ float g_v   [MROWS*KVHEADS*HDIM];
__device__ float g_gate[MROWS*FFN];
__device__ float g_up  [MROWS*FFN];
__device__ float2 g_ropetab[2][SEQ][HDIM/2];

// half activations
__device__ half g_hh [MROWS*DMODEL];
__device__ half g_aoh[MROWS*NHEADS*HDIM];
__device__ half g_gh [MROWS*FFN];
// half weights (converted per launch)
__device__ half gw_q  [LAYERS*NHEADS*DMODEL*HDIM];
__device__ half gw_kv [LAYERS*2*KVHEADS*DMODEL*HDIM];
__device__ half gw_o  [LAYERS*NHEADS*HDIM*DMODEL];
__device__ half gw_gate[(size_t)LAYERS*2*DMODEL*FFN];
__device__ half gw_down[(size_t)LAYERS*FFN*DMODEL];
__device__ half g_embh[(size_t)VOCAB*DMODEL];

// ---------------- helpers ----------------
__device__ __forceinline__ float block_reduce_sum(float v) {
    __shared__ float sh[8];
    int lane = threadIdx.x & 31, wid = threadIdx.x >> 5;
#pragma unroll
    for (int o = 16; o; o >>= 1) v += __shfl_xor_sync(0xffffffffu, v, o);
    if (lane == 0) sh[wid] = v;
    __syncthreads();
    if (wid == 0) {
        float w = (lane < 8) ? sh[lane] : 0.f;
#pragma unroll
        for (int o = 4; o; o >>= 1) w += __shfl_xor_sync(0xffffffffu, w, o);
        if (lane == 0) sh[0] = w;
    }
    __syncthreads();
    return sh[0];
}

__device__ __forceinline__ float fast_tanh(float x) {
    float t = fminf(fmaxf(x, -20.f), 20.f);
    float e = __expf(2.f * t);
    return __fdividef(e - 1.f, e + 1.f);
}

__device__ __forceinline__ uint32_t packh(half lo, half hi) {
    half2 h = __halves2half2(lo, hi);
    return *(uint32_t*)&h;
}

// ---------------- fp32 -> fp16 convert ----------------
__global__ void f2h_kernel(const float* __restrict__ in, half* __restrict__ out, long n) {
    long i = ((long)blockIdx.x * blockDim.x + threadIdx.x) * 4;
    if (i >= n) return;
    float4 v = *(const float4*)(in + i);
    uint2 o;
    o.x = packh(__float2half_rn(v.x), __float2half_rn(v.y));
    o.y = packh(__float2half_rn(v.z), __float2half_rn(v.w));
    *(uint2*)(out + i) = o;
}

// ---------------- embedding ----------------
__global__ void embed_kernel(const int* __restrict__ tokens,
                             const float* __restrict__ emb,
                             float* __restrict__ x, long total) {
    long idx = (long)blockIdx.x * blockDim.x + threadIdx.x;
    if (idx >= total) return;
    long row = idx / DMODEL;
    long d   = idx % DMODEL;
    int tok  = tokens[row];
    x[idx] = emb[(size_t)tok * DMODEL + d] * 48.0f;   // sqrt(2304)=48 exact
}

// ---------------- rmsnorm fp32 -> fp32 (q/k norm) ----------------
__global__ void rmsnorm_kernel(const float* __restrict__ in, float* __restrict__ out,
                               const float* __restrict__ w, int cols) {
    long row = blockIdx.x;
    const float* ip = in + row * cols;
    float* op = out + row * cols;
    float s = 0.f;
    for (int i = threadIdx.x; i < cols; i += blockDim.x) { float v = ip[i]; s += v * v; }
    float tot = block_reduce_sum(s);
    float r = rsqrtf(tot / (float)cols + 1e-6f);
    for (int i = threadIdx.x; i < cols; i += blockDim.x)
        op[i] = ip[i] * r * (1.f + w[i]);
}

// ---------------- rmsnorm fp32 -> fp16 (GEMM A inputs) ----------------
__global__ void rmsnorm_h_kernel(const float* __restrict__ in, half* __restrict__ out,
                                 const float* __restrict__ w, int cols) {
    long row = blockIdx.x;
    const float* ip = in + row * cols;
    half* op = out + row * cols;
    float s = 0.f;
    for (int i = threadIdx.x; i < cols; i += blockDim.x) { float v = ip[i]; s += v * v; }
    float tot = block_reduce_sum(s);
    float r = rsqrtf(tot / (float)cols + 1e-6f);
    for (int i = threadIdx.x; i < cols; i += blockDim.x)
        op[i] = __float2half_rn(ip[i] * r * (1.f + w[i]));
}

// ---------------- x += rmsnorm(h, w) ----------------
__global__ void add_rmsnorm_kernel(float* __restrict__ x, const float* __restrict__ h,
                                   const float* __restrict__ w, int cols) {
    long row = blockIdx.x;
    const float* hp = h + row * cols;
    float* xp = x + row * cols;
    float s = 0.f;
    for (int i = threadIdx.x; i < cols; i += blockDim.x) { float v = hp[i]; s += v * v; }
    float tot = block_reduce_sum(s);
    float r = rsqrtf(tot / (float)cols + 1e-6f);
    for (int i = threadIdx.x; i < cols; i += blockDim.x)
        xp[i] += hp[i] * r * (1.f + w[i]);
}

// ---------------- RoPE table ----------------
__global__ void rope_table_kernel() {
    int idx = blockIdx.x * blockDim.x + threadIdx.x;   // 2*2048*128 total
    int mode = idx >> 18;
    int rem  = idx & 262143;
    int t = rem >> 7, i = rem & 127;
    double base = mode ? 1000000.0 : 10000.0;
    double dv   = mode ? 8.0 : 1.0;
    double frac = (2.0 * (double)i) / (double)HDIM;
    double ts   = exp(frac * log(base));
    double ang  = ((double)t / dv) / ts;
    g_ropetab[mode][t][i] = make_float2((float)sin(ang), (float)cos(ang));
}

__global__ void rope_apply_kernel(float* __restrict__ x, int nh, int mode,
                                  float mul, long total) {
    long idx = (long)blockIdx.x * blockDim.x + threadIdx.x;
    if (idx >= total) return;                       // total = rows * (HDIM/2)
    int i    = (int)(idx & (HDIM/2 - 1));
    long row = idx >> 7;
    int t = (int)((row / nh) % SEQ);
    float2 sc = g_ropetab[mode][t][i];
    float sv = sc.x, cv = sc.y;
    float* p = x + (size_t)row * HDIM;
    float x1 = p[i], x2 = p[i + HDIM/2];
    p[i]          = (x1 * cv - x2 * sv) * mul;
    p[i + HDIM/2] = (x2 * cv + x1 * sv) * mul;
}

// ---------------- GeGLU (fp32 in -> half out) ----------------
__global__ void geglu_kernel(const float* __restrict__ gate, const float* __restrict__ up,
                             half* __restrict__ out, long total) {
    long idx = (long)blockIdx.x * blockDim.x + threadIdx.x;
    if (idx >= total) return;
    float x = gate[idx];
    float x3 = x * x * x;
    float tn = fast_tanh(0.7978845608028654f * (x + 0.044715f * x3));
    out[idx] = __float2half_rn(0.5f * x * (1.f + tn) * up[idx]);
}

// ================= FP16 tensor-core GEMM (cp.async + ldmatrix) =================
// C = A(MxK half row-major) * B ; transB=0: B half [K,N] ; transB=1: B half [N,K] (C=A*B^T)
// 128x128x32 CTA tile, 256 threads, warps 2(M) x 4(N), warp tile 64x32.
__device__ __forceinline__ void cp16(void* smem, const void* gmem) {
    uint32_t s = (uint32_t)__cvta_generic_to_shared(smem);
    asm volatile("cp.async.cg.shared.global [%0], [%1], 16;\n" :: "r"(s), "l"(gmem));
}
__device__ __forceinline__ void ldsm4(uint32_t* r, const void* p) {
    uint32_t a = (uint32_t)__cvta_generic_to_shared(p);
    asm volatile("ldmatrix.sync.aligned.m8n8.x4.shared.b16 {%0,%1,%2,%3}, [%4];"
        : "=r"(r[0]), "=r"(r[1]), "=r"(r[2]), "=r"(r[3]) : "r"(a));
}
__device__ __forceinline__ void ldsm4t(uint32_t* r, const void* p) {
    uint32_t a = (uint32_t)__cvta_generic_to_shared(p);
    asm volatile("ldmatrix.sync.aligned.m8n8.x4.trans.shared.b16 {%0,%1,%2,%3}, [%4];"
        : "=r"(r[0]), "=r"(r[1]), "=r"(r[2]), "=r"(r[3]) : "r"(a));
}
__device__ __forceinline__ void mma_f16(float& c0, float& c1, float& c2, float& c3,
                                        uint32_t a0, uint32_t a1, uint32_t a2, uint32_t a3,
                                        uint32_t b0, uint32_t b1) {
    asm volatile(
        "mma.sync.aligned.m16n8k16.row.col.f32.f16.f16.f32 "
        "{%0,%1,%2,%3}, {%4,%5,%6,%7}, {%8,%9}, {%0,%1,%2,%3};\n"
        : "+f"(c0), "+f"(c1), "+f"(c2), "+f"(c3)
        : "r"(a0), "r"(a1), "r"(a2), "r"(a3), "r"(b0), "r"(b1));
}

struct __align__(16) SmemGemm {
    half As[2][128][40];                 // [m][k] pitch 40: rows 20r%32 -> all-distinct banks
    union {
        half Bnk[2][128][40];            // transB=1: [n][k]
        half Bkn[2][32][136];            // transB=0: [k][n] pitch 136: 4k%32 distinct
    };
};

__global__ __launch_bounds__(256, 2)
void hgemm_kernel(const half* __restrict__ A, int lda, long sA,
                  const half* __restrict__ B, int ldb, long sB,
                  float* __restrict__ C, int ldc, long sC,
                  int Kd, int transB, int capMode)
{
    __shared__ SmemGemm sm;
    const half* Ab = A + (long)blockIdx.z * sA;
    const half* Bb = B + (long)blockIdx.z * sB;
    float*      Cb = C + (long)blockIdx.z * sC;
    const int m0 = blockIdx.y * 128;
    const int n0 = blockIdx.x * 128;
    const int tid = threadIdx.x;
    const int wid = tid >> 5, lane = tid & 31;
    const int g = lane >> 2, t4 = lane & 3;
    const int wm = (wid & 1) * 64;
    const int wn = (wid >> 1) * 32;

    float acc[4][4][4];
#pragma unroll
    for (int i = 0; i < 4; i++)
#pragma unroll
        for (int j = 0; j < 4; j++)
#pragma unroll
            for (int r = 0; r < 4; r++) acc[i][j][r] = 0.f;

    // ---- staging (cp.async): A rows = c&127, kc = (c>>7)*8 (conflict-free STS) ----
    auto stage = [&](int b, int k0) {
#pragma unroll
        for (int i2 = 0; i2 < 2; i2++) {
            int c = tid + 256 * i2;
            int ar = c & 127, akc = (c >> 7) * 8;
            cp16(&sm.As[b][ar][akc], Ab + (size_t)(m0 + ar) * lda + k0 + akc);
            if (transB) {
                cp16(&sm.Bnk[b][ar][akc], Bb + (size_t)(n0 + ar) * ldb + k0 + akc);
            } else {
                int kr = c >> 4, nc = (c & 15) * 8;
                cp16(&sm.Bkn[b][kr][nc], Bb + (size_t)(k0 + kr) * ldb + n0 + nc);
            }
        }
        asm volatile("cp.async.commit_group;\n");
    };

    stage(0, 0);
    int buf = 0;
    const int nK = Kd >> 5;
    for (int kt = 0; kt < nK; kt++) {
        if (kt + 1 < nK) {
            stage(buf ^ 1, (kt + 1) * 32);
            asm volatile("cp.async.wait_group 1;\n");
        } else {
            asm volatile("cp.async.wait_group 0;\n");
        }
        __syncthreads();

#pragma unroll
        for (int ks = 0; ks < 2; ks++) {
            const int ko = ks * 16;
            uint32_t afr[4][4];
#pragma unroll
            for (int i = 0; i < 4; i++)
                ldsm4(afr[i], &sm.As[buf][wm + i * 16 + (lane & 15)][ko + ((lane >> 4) << 3)]);
            uint32_t bfr[4][2];
#pragma unroll
            for (int j2 = 0; j2 < 2; j2++) {
                uint32_t r[4];
                if (transB)
                    ldsm4(r, &sm.Bnk[buf][wn + j2 * 16 + (lane & 15)][ko + ((lane >> 4) << 3)]);
                else
                    ldsm4t(r, &sm.Bkn[buf][ko + (lane & 7) + ((lane & 16) >> 1)]
                                          [wn + j2 * 16 + ((lane >> 3) & 1) * 8]);
                bfr[2 * j2][0] = r[0]; bfr[2 * j2 + 1][0] = r[1];
                bfr[2 * j2][1] = r[2]; bfr[2 * j2 + 1][1] = r[3];
            }
#pragma unroll
            for (int i = 0; i < 4; i++)
#pragma unroll
                for (int j = 0; j < 4; j++)
                    mma_f16(acc[i][j][0], acc[i][j][1], acc[i][j][2], acc[i][j][3],
                            afr[i][0], afr[i][1], afr[i][2], afr[i][3],
                            bfr[j][0], bfr[j][1]);
        }
        __syncthreads();
        buf ^= 1;
    }

    // ---- epilogue ----
#pragma unroll
    for (int i = 0; i < 4; i++) {
#pragma unroll
        for (int j = 0; j < 4; j++) {
            int row0 = m0 + wm + i * 16 + g;
            int col  = n0 + wn + j * 8 + 2 * t4;
            float c0 = acc[i][j][0], c1 = acc[i][j][1];
            float c2 = acc[i][j][2], c3 = acc[i][j][3];
            if (capMode) {
                c0 = FINAL_CAP * fast_tanh(c0 * (1.f / FINAL_CAP));
                c1 = FINAL_CAP * fast_tanh(c1 * (1.f / FINAL_CAP));
                c2 = FINAL_CAP * fast_tanh(c2 * (1.f / FINAL_CAP));
                c3 = FINAL_CAP * fast_tanh(c3 * (1.f / FINAL_CAP));
            }
            *(float2*)(Cb + (size_t)row0 * ldc + col)       = make_float2(c0, c1);
            *(float2*)(Cb + (size_t)(row0 + 8) * ldc + col) = make_float2(c2, c3);
        }
    }
}

// ---------------- flash attention with soft cap + sliding window ----------------
#define ST 16
__global__ __launch_bounds__(256)
void attn_kernel(const float* __restrict__ q, const float* __restrict__ k,
                 const float* __restrict__ v, half* __restrict__ out, int isLocal)
{
    __shared__ float ks[ST][HDIM];
    __shared__ float vs[ST][HDIM];
    int b = blockIdx.z, n = blockIdx.y;
    int t0 = blockIdx.x * 16;
    int kh = n >> 1;                       // GQA: group size 2
    int tid = threadIdx.x, wid = tid >> 5, lane = tid & 31;
    int tq = t0 + wid * 2;

    float qr[2][8];
#pragma unroll
    for (int qi = 0; qi < 2; qi++) {
        const float* qp = q + (((size_t)(b * SEQ + tq + qi) * NHEADS + n) * HDIM) + lane * 8;
        float4 a = *(const float4*)qp;
        float4 b4 = *(const float4*)(qp + 4);
        qr[qi][0] = a.x;  qr[qi][1] = a.y;  qr[qi][2] = a.z;  qr[qi][3] = a.w;
        qr[qi][4] = b4.x; qr[qi][5] = b4.y; qr[qi][6] = b4.z; qr[qi][7] = b4.w;
    }
    float m[2] = {-1e30f, -1e30f};
    float lsum[2] = {0.f, 0.f};
    float acc[2][8];
#pragma unroll
    for (int qi = 0; qi < 2; qi++)
#pragma unroll
        for (int j = 0; j < 8; j++) acc[qi][j] = 0.f;

    int sEnd = t0 + 15;
    int sLo = 0;
    if (isLocal) { sLo = t0 - (WINDOW_SZ - 1); if (sLo < 0) sLo = 0; }
    sLo &= ~(ST - 1);

    int lr = tid >> 4, lc = tid & 15;
    for (int sB = sLo; sB <= sEnd; sB += ST) {
        const float* kp = k + ((size_t)(b * SEQ + sB + lr) * KVHEADS + kh) * HDIM;
        const float* vp = v + ((size_t)(b * SEQ + sB + lr) * KVHEADS + kh) * HDIM;
#pragma unroll
        for (int j = 0; j < 4; j++) {
            int c = (lc + j * 16) * 4;
            *(float4*)&ks[lr][c] = *(const float4*)(kp + c);
            *(float4*)&vs[lr][c] = *(const float4*)(vp + c);
        }
        __syncthreads();
#pragma unroll 4
        for (int ss = 0; ss < ST; ss++) {
            int s = sB + ss;
            float kk[8];
            *(float4*)&kk[0] = *(float4*)&ks[ss][lane * 8];
            *(float4*)&kk[4] = *(float4*)&ks[ss][lane * 8 + 4];
            float d0 = 0.f, d1 = 0.f;
#pragma unroll
            for (int j = 0; j < 8; j++) { d0 += qr[0][j] * kk[j]; d1 += qr[1][j] * kk[j]; }
#pragma unroll
            for (int o = 16; o; o >>= 1) {
                d0 += __shfl_xor_sync(0xffffffffu, d0, o);
                d1 += __shfl_xor_sync(0xffffffffu, d1, o);
            }
            float vv[8];
            *(float4*)&vv[0] = *(float4*)&vs[ss][lane * 8];
            *(float4*)&vv[4] = *(float4*)&vs[ss][lane * 8 + 4];
#pragma unroll
            for (int qi = 0; qi < 2; qi++) {
                int t = tq + qi;
                bool valid = (s <= t) && (!isLocal || (t - s) < WINDOW_SZ);
                if (valid) {
                    float dd = qi ? d1 : d0;
                    float lg = ATTN_CAP * fast_tanh(dd * (1.f / ATTN_CAP));
                    if (lg > m[qi]) {      // warp-uniform (dd uniform after butterfly)
                        float corr = __expf(m[qi] - lg);
                        m[qi] = lg;
                        lsum[qi] *= corr;
#pragma unroll
                        for (int j = 0; j < 8; j++) acc[qi][j] *= corr;
                    }
                    float p = __expf(lg - m[qi]);
                    lsum[qi] += p;
#pragma unroll
                    for (int j = 0; j < 8; j++) acc[qi][j] += p * vv[j];
                }
            }
        }
        __syncthreads();
    }
#pragma unroll
    for (int qi = 0; qi < 2; qi++) {
        float inv = 1.f / lsum[qi];
        half* op = out + (((size_t)(b * SEQ + tq + qi) * NHEADS + n) * HDIM) + lane * 8;
        uint2 p0, p1;
        p0.x = packh(__float2half_rn(acc[qi][0]*inv), __float2half_rn(acc[qi][1]*inv));
        p0.y = packh(__float2half_rn(acc[qi][2]*inv), __float2half_rn(acc[qi][3]*inv));
        p1.x = packh(__float2half_rn(acc[qi][4]*inv), __float2half_rn(acc[qi][5]*inv));
        p1.y = packh(__float2half_rn(acc[qi][6]*inv), __float2half_rn(acc[qi][7]*inv));
        *(uint2*)op       = p0;
        *(uint2*)(op + 4) = p1;
    }
}

// ---------------- host launcher ----------------
static inline void conv(const float* src, half* dst, long n) {
    f2h_kernel<<<(unsigned)((n / 4 + 255) / 256), 256>>>(src, dst, n);
}

extern "C" void kernel_launch(void* const* d_in, const int* in_sizes, int n_in,
                              void* d_out, int out_size)
{
    const int*   tokens    = (const int*)  d_in[0];
    const float* emb       = (const float*)d_in[1];
    const float* w_q       = (const float*)d_in[2];
    const float* w_kv      = (const float*)d_in[3];
    const float* w_o       = (const float*)d_in[4];
    const float* attn_nrm  = (const float*)d_in[5];
    const float* pattn_nrm = (const float*)d_in[6];
    const float* ffw_nrm   = (const float*)d_in[7];
    const float* pffw_nrm  = (const float*)d_in[8];
    const float* q_nrm     = (const float*)d_in[9];
    const float* k_nrm     = (const float*)d_in[10];
    const float* gate_w    = (const float*)d_in[11];
    const float* down_w    = (const float*)d_in[12];
    const float* final_nrm = (const float*)d_in[13];
    float* out = (float*)d_out;

    float *x, *h, *q, *k, *v, *gate, *up;
    half *hh, *aoh, *gh, *wqh, *wkvh, *woh, *wgh, *wdh, *embh;
    cudaGetSymbolAddress((void**)&x,    g_x);
    cudaGetSymbolAddress((void**)&h,    g_h);
    cudaGetSymbolAddress((void**)&q,    g_q);
    cudaGetSymbolAddress((void**)&k,    g_k);
    cudaGetSymbolAddress((void**)&v,    g_v);
    cudaGetSymbolAddress((void**)&gate, g_gate);
    cudaGetSymbolAddress((void**)&up,   g_up);
    cudaGetSymbolAddress((void**)&hh,   g_hh);
    cudaGetSymbolAddress((void**)&aoh,  g_aoh);
    cudaGetSymbolAddress((void**)&gh,   g_gh);
    cudaGetSymbolAddress((void**)&wqh,  gw_q);
    cudaGetSymbolAddress((void**)&wkvh, gw_kv);
    cudaGetSymbolAddress((void**)&woh,  gw_o);
    cudaGetSymbolAddress((void**)&wgh,  gw_gate);
    cudaGetSymbolAddress((void**)&wdh,  gw_down);
    cudaGetSymbolAddress((void**)&embh, g_embh);

    // weight conversions (deterministic, every launch)
    conv(w_q,    wqh,  (long)LAYERS * NHEADS * DMODEL * HDIM);
    conv(w_kv,   wkvh, (long)LAYERS * 2 * KVHEADS * DMODEL * HDIM);
    conv(w_o,    woh,  (long)LAYERS * NHEADS * HDIM * DMODEL);
    conv(gate_w, wgh,  (long)LAYERS * 2 * DMODEL * FFN);
    conv(down_w, wdh,  (long)LAYERS * FFN * DMODEL);
    conv(emb,    embh, (long)VOCAB * DMODEL);

    // RoPE table
    rope_table_kernel<<<2 * SEQ * (HDIM/2) / 256, 256>>>();

    // embedding
    {
        long total = (long)MROWS * DMODEL;
        embed_kernel<<<(unsigned)((total + 255) / 256), 256>>>(tokens, emb, x, total);
    }

    for (int l = 0; l < LAYERS; l++) {
        int isLocal = (l % 2 == 0);
        int mode    = isLocal ? 0 : 1;

        // attn pre-norm -> half
        rmsnorm_h_kernel<<<MROWS, 256>>>(x, hh, attn_nrm + (size_t)l * DMODEL, DMODEL);

        // q projection: 8 batched GEMMs [4096,2304]x[2304,256]
        {
            dim3 grid(HDIM / 128, MROWS / 128, NHEADS);
            hgemm_kernel<<<grid, 256>>>(hh, DMODEL, 0,
                wqh + (size_t)l * NHEADS * DMODEL * HDIM, HDIM, (long)DMODEL * HDIM,
                q, NHEADS * HDIM, HDIM, DMODEL, 0, 0);
        }
        // k / v projections
        {
            dim3 grid(HDIM / 128, MROWS / 128, KVHEADS);
            hgemm_kernel<<<grid, 256>>>(hh, DMODEL, 0,
                wkvh + (size_t)(l * 2 + 0) * KVHEADS * DMODEL * HDIM, HDIM, (long)DMODEL * HDIM,
                k, KVHEADS * HDIM, HDIM, DMODEL, 0, 0);
            hgemm_kernel<<<grid, 256>>>(hh, DMODEL, 0,
                wkvh + (size_t)(l * 2 + 1) * KVHEADS * DMODEL * HDIM, HDIM, (long)DMODEL * HDIM,
                v, KVHEADS * HDIM, HDIM, DMODEL, 0, 0);
        }
        // qk-norm (fp32 in-place)
        rmsnorm_kernel<<<MROWS * NHEADS, 256>>>(q, q, q_nrm + (size_t)l * HDIM, HDIM);
        rmsnorm_kernel<<<MROWS * KVHEADS, 256>>>(k, k, k_nrm + (size_t)l * HDIM, HDIM);
        // rope (+ H^-0.5 scale on q)
        {
            long tq = (long)MROWS * NHEADS * (HDIM / 2);
            long tk = (long)MROWS * KVHEADS * (HDIM / 2);
            rope_apply_kernel<<<(unsigned)((tq + 255) / 256), 256>>>(q, NHEADS,  mode, 0.0625f, tq);
            rope_apply_kernel<<<(unsigned)((tk + 255) / 256), 256>>>(k, KVHEADS, mode, 1.0f,    tk);
        }
        // attention -> half
        {
            dim3 grid(SEQ / 16, NHEADS, BATCH);
            attn_kernel<<<grid, 256>>>(q, k, v, aoh, isLocal);
        }
        // output projection: [4096,2048] x [2048,2304]
        {
            dim3 grid(DMODEL / 128, MROWS / 128, 1);
            hgemm_kernel<<<grid, 256>>>(aoh, NHEADS * HDIM, 0,
                woh + (size_t)l * NHEADS * HDIM * DMODEL, DMODEL, 0,
                h, DMODEL, 0, NHEADS * HDIM, 0, 0);
        }
        add_rmsnorm_kernel<<<MROWS, 256>>>(x, h, pattn_nrm + (size_t)l * DMODEL, DMODEL);

        // MLP
        rmsnorm_h_kernel<<<MROWS, 256>>>(x, hh, ffw_nrm + (size_t)l * DMODEL, DMODEL);
        {
            dim3 grid(FFN / 128, MROWS / 128, 1);
            hgemm_kernel<<<grid, 256>>>(hh, DMODEL, 0,
                wgh + (size_t)(l * 2 + 0) * DMODEL * FFN, FFN, 0,
                gate, FFN, 0, DMODEL, 0, 0);
            hgemm_kernel<<<grid, 256>>>(hh, DMODEL, 0,
                wgh + (size_t)(l * 2 + 1) * DMODEL * FFN, FFN, 0,
                up, FFN, 0, DMODEL, 0, 0);
        }
        {
            long total = (long)MROWS * FFN;
            geglu_kernel<<<(unsigned)((total + 255) / 256), 256>>>(gate, up, gh, total);
        }
        {
            dim3 grid(DMODEL / 128, MROWS / 128, 1);
            hgemm_kernel<<<grid, 256>>>(gh, FFN, 0,
                wdh + (size_t)l * FFN * DMODEL, DMODEL, 0,
                h, DMODEL, 0, FFN, 0, 0);
        }
        add_rmsnorm_kernel<<<MROWS, 256>>>(x, h, pffw_nrm + (size_t)l * DMODEL, DMODEL);
    }

    // final norm + tied-embedding decode with soft cap (B = emb [V,D] = [N,K], transB=1)
    rmsnorm_h_kernel<<<MROWS, 256>>>(x, hh, final_nrm, DMODEL);
    {
        dim3 grid(VOCAB / 128, MROWS / 128, 1);
        hgemm_kernel<<<grid, 256>>>(hh, DMODEL, 0,
            embh, DMODEL, 0,
            out, VOCAB, 0, DMODEL, 1, 1);
    }
}

// round 15
// speedup vs baseline: 3.8754x; 1.1101x over previous
#include <cuda_runtime.h>
#include <cuda_fp16.h>
#include <math.h>
#include <stdint.h>

// ---------------- problem dims ----------------
#define LAYERS   4
#define VOCAB    32000
#define DMODEL   2304
#define FFN      9216
#define NHEADS   8
#define KVHEADS  4
#define HDIM     256
#define BATCH    2
#define SEQ      2048
#define MROWS    (BATCH*SEQ)      // 4096
#define WINDOW_SZ 1024
#define ATTN_CAP 50.0f
#define FINAL_CAP 30.0f

// ---------------- static scratch (no allocations allowed) ----------------
__device__ float g_x [MROWS*DMODEL];
__device__ float g_h [MROWS*DMODEL];
__device__ float g_q [MROWS*NHEADS*HDIM];          // [row][head*256]
__device__ float g_kv[MROWS*2*KVHEADS*HDIM];       // [row][ k:0..1023 | v:1024..2047 ]
__device__ float g_gu[(size_t)MROWS*2*FFN];        // [row][ gate:0..9215 | up:9216..18431 ]
__device__ float2 g_ropetab[2][SEQ][HDIM/2];

// half activations
__device__ half g_hh [MROWS*DMODEL];
__device__ half g_aoh[MROWS*NHEADS*HDIM];
__device__ half g_gh [MROWS*FFN];
// half TRANSPOSED weights (converted per launch); all stored [N][K]
__device__ half gw_q  [LAYERS*NHEADS*DMODEL*HDIM];
__device__ half gw_kv [LAYERS*2*KVHEADS*DMODEL*HDIM];
__device__ half gw_o  [LAYERS*NHEADS*HDIM*DMODEL];
__device__ half gw_gate[(size_t)LAYERS*2*DMODEL*FFN];
__device__ half gw_down[(size_t)LAYERS*FFN*DMODEL];
__device__ half g_embh[(size_t)VOCAB*DMODEL];

// ---------------- helpers ----------------
__device__ __forceinline__ float block_reduce_sum(float v) {
    __shared__ float sh[8];
    int lane = threadIdx.x & 31, wid = threadIdx.x >> 5;
#pragma unroll
    for (int o = 16; o; o >>= 1) v += __shfl_xor_sync(0xffffffffu, v, o);
    if (lane == 0) sh[wid] = v;
    __syncthreads();
    if (wid == 0) {
        float w = (lane < 8) ? sh[lane] : 0.f;
#pragma unroll
        for (int o = 4; o; o >>= 1) w += __shfl_xor_sync(0xffffffffu, w, o);
        if (lane == 0) sh[0] = w;
    }
    __syncthreads();
    return sh[0];
}

__device__ __forceinline__ float fast_tanh(float x) {
    float t = fminf(fmaxf(x, -20.f), 20.f);
    float e = __expf(2.f * t);
    return __fdividef(e - 1.f, e + 1.f);
}

__device__ __forceinline__ uint32_t packh(half lo, half hi) {
    half2 h = __halves2half2(lo, hi);
    return *(uint32_t*)&h;
}

// ---------------- fp32 -> fp16 convert (no transpose) ----------------
__global__ void f2h_kernel(const float* __restrict__ in, half* __restrict__ out, long n) {
    long i = ((long)blockIdx.x * blockDim.x + threadIdx.x) * 4;
    if (i >= n) return;
    float4 v = *(const float4*)(in + i);
    uint2 o;
    o.x = packh(__float2half_rn(v.x), __float2half_rn(v.y));
    o.y = packh(__float2half_rn(v.z), __float2half_rn(v.w));
    *(uint2*)(out + i) = o;
}

// ---------------- fp32 [R][C] -> fp16 transposed [C][R], batched over z ----------------
__global__ void tr_f2h_kernel(const float* __restrict__ in, half* __restrict__ out,
                              int R, int C) {
    __shared__ float t[32][33];
    long z = blockIdx.z;
    const float* I = in + z * (long)R * C;
    half* O = out + z * (long)R * C;
    int r0 = blockIdx.y * 32, c0 = blockIdx.x * 32;
    int tx = threadIdx.x & 31, ty = threadIdx.x >> 5;   // 256 threads: ty 0..7
#pragma unroll
    for (int i = 0; i < 32; i += 8)
        t[ty + i][tx] = I[(size_t)(r0 + ty + i) * C + c0 + tx];
    __syncthreads();
#pragma unroll
    for (int i = 0; i < 32; i += 8)
        O[(size_t)(c0 + ty + i) * R + r0 + tx] = __float2half_rn(t[tx][ty + i]);
}

// ---------------- embedding ----------------
__global__ void embed_kernel(const int* __restrict__ tokens,
                             const float* __restrict__ emb,
                             float* __restrict__ x, long total) {
    long idx = (long)blockIdx.x * blockDim.x + threadIdx.x;
    if (idx >= total) return;
    long row = idx / DMODEL;
    long d   = idx % DMODEL;
    int tok  = tokens[row];
    x[idx] = emb[(size_t)tok * DMODEL + d] * 48.0f;   // sqrt(2304)=48 exact
}

// ---------------- rmsnorm fp32 -> fp32 (contiguous 'cols' chunks) ----------------
__global__ void rmsnorm_kernel(const float* __restrict__ in, float* __restrict__ out,
                               const float* __restrict__ w, int cols) {
    long row = blockIdx.x;
    const float* ip = in + row * cols;
    float* op = out + row * cols;
    float s = 0.f;
    for (int i = threadIdx.x; i < cols; i += blockDim.x) { float v = ip[i]; s += v * v; }
    float tot = block_reduce_sum(s);
    float r = rsqrtf(tot / (float)cols + 1e-6f);
    for (int i = threadIdx.x; i < cols; i += blockDim.x)
        op[i] = ip[i] * r * (1.f + w[i]);
}

// ---------------- rmsnorm for k-heads inside kv buffer (in-place) ----------------
__global__ void rmsnorm_kv_kernel(float* __restrict__ kv, const float* __restrict__ w) {
    int b = blockIdx.x;                       // 0 .. MROWS*KVHEADS-1
    float* p = kv + (size_t)(b >> 2) * 2048 + (b & 3) * 256;
    float s = 0.f;
    for (int i = threadIdx.x; i < 256; i += blockDim.x) { float v = p[i]; s += v * v; }
    float tot = block_reduce_sum(s);
    float r = rsqrtf(tot / 256.f + 1e-6f);
    for (int i = threadIdx.x; i < 256; i += blockDim.x)
        p[i] = p[i] * r * (1.f + w[i]);
}

// ---------------- rmsnorm fp32 -> fp16 ----------------
__global__ void rmsnorm_h_kernel(const float* __restrict__ in, half* __restrict__ out,
                                 const float* __restrict__ w, int cols) {
    long row = blockIdx.x;
    const float* ip = in + row * cols;
    half* op = out + row * cols;
    float s = 0.f;
    for (int i = threadIdx.x; i < cols; i += blockDim.x) { float v = ip[i]; s += v * v; }
    float tot = block_reduce_sum(s);
    float r = rsqrtf(tot / (float)cols + 1e-6f);
    for (int i = threadIdx.x; i < cols; i += blockDim.x)
        op[i] = __float2half_rn(ip[i] * r * (1.f + w[i]));
}

// ---------------- x += rmsnorm(h, w) ----------------
__global__ void add_rmsnorm_kernel(float* __restrict__ x, const float* __restrict__ h,
                                   const float* __restrict__ w, int cols) {
    long row = blockIdx.x;
    const float* hp = h + row * cols;
    float* xp = x + row * cols;
    float s = 0.f;
    for (int i = threadIdx.x; i < cols; i += blockDim.x) { float v = hp[i]; s += v * v; }
    float tot = block_reduce_sum(s);
    float r = rsqrtf(tot / (float)cols + 1e-6f);
    for (int i = threadIdx.x; i < cols; i += blockDim.x)
        xp[i] += hp[i] * r * (1.f + w[i]);
}

// ---------------- RoPE table ----------------
__global__ void rope_table_kernel() {
    int idx = blockIdx.x * blockDim.x + threadIdx.x;   // 2*2048*128 total
    int mode = idx >> 18;
    int rem  = idx & 262143;
    int t = rem >> 7, i = rem & 127;
    double base = mode ? 1000000.0 : 10000.0;
    double dv   = mode ? 8.0 : 1.0;
    double frac = (2.0 * (double)i) / (double)HDIM;
    double ts   = exp(frac * log(base));
    double ang  = ((double)t / dv) / ts;
    g_ropetab[mode][t][i] = make_float2((float)sin(ang), (float)cos(ang));
}

// rope on q: [row][head*256], chunk c = row*8+head
__global__ void rope_q_kernel(float* __restrict__ q, int mode, long total) {
    long idx = (long)blockIdx.x * blockDim.x + threadIdx.x;
    if (idx >= total) return;                       // total = MROWS*NHEADS*128
    int i   = (int)(idx & 127);
    long c  = idx >> 7;
    int t = (int)((c >> 3) % SEQ);
    float2 sc = g_ropetab[mode][t][i];
    float* p = q + (size_t)c * HDIM;
    float x1 = p[i], x2 = p[i + 128];
    p[i]       = (x1 * sc.y - x2 * sc.x) * 0.0625f;   // * H^-0.5
    p[i + 128] = (x2 * sc.y + x1 * sc.x) * 0.0625f;
}

// rope on k inside kv buffer
__global__ void rope_kv_kernel(float* __restrict__ kv, int mode, long total) {
    long idx = (long)blockIdx.x * blockDim.x + threadIdx.x;
    if (idx >= total) return;                       // total = MROWS*KVHEADS*128
    int i   = (int)(idx & 127);
    long c  = idx >> 7;                             // row*4 + khead
    int t = (int)((c >> 2) % SEQ);
    float2 sc = g_ropetab[mode][t][i];
    float* p = kv + (size_t)(c >> 2) * 2048 + (c & 3) * 256;
    float x1 = p[i], x2 = p[i + 128];
    p[i]       = x1 * sc.y - x2 * sc.x;
    p[i + 128] = x2 * sc.y + x1 * sc.x;
}

// ---------------- GeGLU (gu fp32 in -> half out) ----------------
__global__ void geglu_kernel(const float* __restrict__ gu, half* __restrict__ out, long total) {
    long idx = (long)blockIdx.x * blockDim.x + threadIdx.x;
    if (idx >= total) return;                       // total = MROWS*FFN
    long row = idx / FFN, col = idx % FFN;
    float x = gu[row * (2 * FFN) + col];
    float u = gu[row * (2 * FFN) + FFN + col];
    float x3 = x * x * x;
    float tn = fast_tanh(0.7978845608028654f * (x + 0.044715f * x3));
    out[idx] = __float2half_rn(0.5f * x * (1.f + tn) * u);
}

// ================= FP16 HMMA GEMM: C[M][N] = A[M][K] * B[N][K]^T =================
// CTA tile 128(M) x 256(N), K-tile 32, 3-stage cp.async, 256 threads (2x4 warps, 64x64 warp tile)
// smem rows: 40 halves (80B) pitch -> ldmatrix banks 20r%32 all-distinct (conflict-free)
#define SM_APITCH 40
#define SM_ASTAGE (128*SM_APITCH*2)      // 10240 B
#define SM_BSTAGE (256*SM_APITCH*2)      // 20480 B
#define SM_BBASE  (3*SM_ASTAGE)          // 30720
#define SM_TOTAL  (SM_BBASE + 3*SM_BSTAGE)   // 92160 B

__device__ __forceinline__ void cp16_s(uint32_t saddr, const void* g) {
    asm volatile("cp.async.cg.shared.global [%0], [%1], 16;\n" :: "r"(saddr), "l"(g));
}
__device__ __forceinline__ void ldsm4_s(uint32_t* r, uint32_t a) {
    asm volatile("ldmatrix.sync.aligned.m8n8.x4.shared.b16 {%0,%1,%2,%3}, [%4];"
        : "=r"(r[0]), "=r"(r[1]), "=r"(r[2]), "=r"(r[3]) : "r"(a));
}
__device__ __forceinline__ void mma_f16(float& c0, float& c1, float& c2, float& c3,
                                        uint32_t a0, uint32_t a1, uint32_t a2, uint32_t a3,
                                        uint32_t b0, uint32_t b1) {
    asm volatile(
        "mma.sync.aligned.m16n8k16.row.col.f32.f16.f16.f32 "
        "{%0,%1,%2,%3}, {%4,%5,%6,%7}, {%8,%9}, {%0,%1,%2,%3};\n"
        : "+f"(c0), "+f"(c1), "+f"(c2), "+f"(c3)
        : "r"(a0), "r"(a1), "r"(a2), "r"(a3), "r"(b0), "r"(b1));
}

__global__ __launch_bounds__(256, 1)
void hgemm_kernel(const half* __restrict__ A, int lda,
                  const half* __restrict__ B, int ldb,
                  float* __restrict__ C, int ldc,
                  int Kd, int capMode)
{
    extern __shared__ __align__(16) uint8_t smem[];
    uint32_t sbase = (uint32_t)__cvta_generic_to_shared(smem);
    const int m0 = blockIdx.y * 128;
    const int n0 = blockIdx.x * 256;
    const int tid = threadIdx.x;
    const int wid = tid >> 5, lane = tid & 31;
    const int g = lane >> 2, t4 = lane & 3;
    const int wm = (wid & 1) * 64;
    const int wn = (wid >> 1) * 64;

    float acc[4][8][4];
#pragma unroll
    for (int i = 0; i < 4; i++)
#pragma unroll
        for (int j = 0; j < 8; j++)
#pragma unroll
            for (int r = 0; r < 4; r++) acc[i][j][r] = 0.f;

    // stage: A 512 chunks (2/thread), B 1024 chunks (4/thread); chunk = row + 8-half k-piece
    auto stage = [&](int st, int k0) {
        uint32_t abase = sbase + st * SM_ASTAGE;
        uint32_t bbase = sbase + SM_BBASE + st * SM_BSTAGE;
#pragma unroll
        for (int i = 0; i < 2; i++) {
            int c = tid + 256 * i;
            int row = c >> 2, kc = (c & 3) * 8;
            cp16_s(abase + row * 80 + kc * 2, A + (size_t)(m0 + row) * lda + k0 + kc);
        }
#pragma unroll
        for (int i = 0; i < 4; i++) {
            int c = tid + 256 * i;
            int row = c >> 2, kc = (c & 3) * 8;
            cp16_s(bbase + row * 80 + kc * 2, B + (size_t)(n0 + row) * ldb + k0 + kc);
        }
        asm volatile("cp.async.commit_group;\n");
    };

    const int nK = Kd >> 5;
    stage(0, 0);
    stage(1, 32);
    for (int kt = 0; kt < nK; kt++) {
        __syncthreads();                       // all warps done with buffer (kt+2)%3
        if (kt + 2 < nK) stage((kt + 2) % 3, (kt + 2) * 32);
        if (kt + 2 < nK)      { asm volatile("cp.async.wait_group 2;\n"); }
        else if (kt + 1 < nK) { asm volatile("cp.async.wait_group 1;\n"); }
        else                  { asm volatile("cp.async.wait_group 0;\n"); }
        __syncthreads();                       // group kt visible to all

        const int buf = kt % 3;
        uint32_t abase = sbase + buf * SM_ASTAGE;
        uint32_t bbase = sbase + SM_BBASE + buf * SM_BSTAGE;
#pragma unroll
        for (int ks = 0; ks < 2; ks++) {
            const int ko = ks * 16;
            uint32_t afr[4][4];
#pragma unroll
            for (int i = 0; i < 4; i++)
                ldsm4_s(afr[i], abase + (wm + i * 16 + (lane & 15)) * 80
                                      + (ko + ((lane >> 4) << 3)) * 2);
            uint32_t bfr[8][2];
#pragma unroll
            for (int j2 = 0; j2 < 4; j2++) {
                uint32_t r[4];
                ldsm4_s(r, bbase + (wn + j2 * 16 + (lane & 15)) * 80
                                 + (ko + ((lane >> 4) << 3)) * 2);
                bfr[2 * j2][0] = r[0]; bfr[2 * j2 + 1][0] = r[1];
                bfr[2 * j2][1] = r[2]; bfr[2 * j2 + 1][1] = r[3];
            }
#pragma unroll
            for (int i = 0; i < 4; i++)
#pragma unroll
                for (int j = 0; j < 8; j++)
                    mma_f16(acc[i][j][0], acc[i][j][1], acc[i][j][2], acc[i][j][3],
                            afr[i][0], afr[i][1], afr[i][2], afr[i][3],
                            bfr[j][0], bfr[j][1]);
        }
    }

    // ---- epilogue ----
#pragma unroll
    for (int i = 0; i < 4; i++) {
#pragma unroll
        for (int j = 0; j < 8; j++) {
            int row0 = m0 + wm + i * 16 + g;
            int col  = n0 + wn + j * 8 + 2 * t4;
            float c0 = acc[i][j][0], c1 = acc[i][j][1];
            float c2 = acc[i][j][2], c3 = acc[i][j][3];
            if (capMode) {
                c0 = FINAL_CAP * fast_tanh(c0 * (1.f / FINAL_CAP));
                c1 = FINAL_CAP * fast_tanh(c1 * (1.f / FINAL_CAP));
                c2 = FINAL_CAP * fast_tanh(c2 * (1.f / FINAL_CAP));
                c3 = FINAL_CAP * fast_tanh(c3 * (1.f / FINAL_CAP));
            }
            *(float2*)(C + (size_t)row0 * ldc + col)       = make_float2(c0, c1);
            *(float2*)(C + (size_t)(row0 + 8) * ldc + col) = make_float2(c2, c3);
        }
    }
}

// ---------------- flash attention with soft cap + sliding window ----------------
#define ST 16
__global__ __launch_bounds__(256)
void attn_kernel(const float* __restrict__ q, const float* __restrict__ kv,
                 half* __restrict__ out, int isLocal)
{
    __shared__ float ks[ST][HDIM];
    __shared__ float vs[ST][HDIM];
    int b = blockIdx.z, n = blockIdx.y;
    int t0 = blockIdx.x * 16;
    int kh = n >> 1;                       // GQA: group size 2
    int tid = threadIdx.x, wid = tid >> 5, lane = tid & 31;
    int tq = t0 + wid * 2;

    float qr[2][8];
#pragma unroll
    for (int qi = 0; qi < 2; qi++) {
        const float* qp = q + ((size_t)(b * SEQ + tq + qi) * (NHEADS * HDIM)) + n * HDIM + lane * 8;
        float4 a = *(const float4*)qp;
        float4 b4 = *(const float4*)(qp + 4);
        qr[qi][0] = a.x;  qr[qi][1] = a.y;  qr[qi][2] = a.z;  qr[qi][3] = a.w;
        qr[qi][4] = b4.x; qr[qi][5] = b4.y; qr[qi][6] = b4.z; qr[qi][7] = b4.w;
    }
    float m[2] = {-1e30f, -1e30f};
    float lsum[2] = {0.f, 0.f};
    float acc[2][8];
#pragma unroll
    for (int qi = 0; qi < 2; qi++)
#pragma unroll
        for (int j = 0; j < 8; j++) acc[qi][j] = 0.f;

    int sEnd = t0 + 15;
    int sLo = 0;
    if (isLocal) { sLo = t0 - (WINDOW_SZ - 1); if (sLo < 0) sLo = 0; }
    sLo &= ~(ST - 1);

    int lr = tid >> 4, lc = tid & 15;
    for (int sB = sLo; sB <= sEnd; sB += ST) {
        const float* kp = kv + (size_t)(b * SEQ + sB + lr) * 2048 + kh * HDIM;
        const float* vp = kp + 1024;
#pragma unroll
        for (int j = 0; j < 4; j++) {
            int c = (lc + j * 16) * 4;
            *(float4*)&ks[lr][c] = *(const float4*)(kp + c);
            *(float4*)&vs[lr][c] = *(const float4*)(vp + c);
        }
        __syncthreads();
#pragma unroll 4
        for (int ss = 0; ss < ST; ss++) {
            int s = sB + ss;
            float kk[8];
            *(float4*)&kk[0] = *(float4*)&ks[ss][lane * 8];
            *(float4*)&kk[4] = *(float4*)&ks[ss][lane * 8 + 4];
            float d0 = 0.f, d1 = 0.f;
#pragma unroll
            for (int j = 0; j < 8; j++) { d0 += qr[0][j] * kk[j]; d1 += qr[1][j] * kk[j]; }
#pragma unroll
            for (int o = 16; o; o >>= 1) {
                d0 += __shfl_xor_sync(0xffffffffu, d0, o);
                d1 += __shfl_xor_sync(0xffffffffu, d1, o);
            }
            float vv[8];
            *(float4*)&vv[0] = *(float4*)&vs[ss][lane * 8];
            *(float4*)&vv[4] = *(float4*)&vs[ss][lane * 8 + 4];
#pragma unroll
            for (int qi = 0; qi < 2; qi++) {
                int t = tq + qi;
                bool valid = (s <= t) && (!isLocal || (t - s) < WINDOW_SZ);
                if (valid) {
                    float dd = qi ? d1 : d0;
                    float lg = ATTN_CAP * fast_tanh(dd * (1.f / ATTN_CAP));
                    if (lg > m[qi]) {      // warp-uniform (dd uniform after butterfly)
                        float corr = __expf(m[qi] - lg);
                        m[qi] = lg;
                        lsum[qi] *= corr;
#pragma unroll
                        for (int j = 0; j < 8; j++) acc[qi][j] *= corr;
                    }
                    float p = __expf(lg - m[qi]);
                    lsum[qi] += p;
#pragma unroll
                    for (int j = 0; j < 8; j++) acc[qi][j] += p * vv[j];
                }
            }
        }
        __syncthreads();
    }
#pragma unroll
    for (int qi = 0; qi < 2; qi++) {
        float inv = 1.f / lsum[qi];
        half* op = out + ((size_t)(b * SEQ + tq + qi) * (NHEADS * HDIM)) + n * HDIM + lane * 8;
        uint2 p0, p1;
        p0.x = packh(__float2half_rn(acc[qi][0]*inv), __float2half_rn(acc[qi][1]*inv));
        p0.y = packh(__float2half_rn(acc[qi][2]*inv), __float2half_rn(acc[qi][3]*inv));
        p1.x = packh(__float2half_rn(acc[qi][4]*inv), __float2half_rn(acc[qi][5]*inv));
        p1.y = packh(__float2half_rn(acc[qi][6]*inv), __float2half_rn(acc[qi][7]*inv));
        *(uint2*)op       = p0;
        *(uint2*)(op + 4) = p1;
    }
}

// ---------------- host launcher ----------------
extern "C" void kernel_launch(void* const* d_in, const int* in_sizes, int n_in,
                              void* d_out, int out_size)
{
    const int*   tokens    = (const int*)  d_in[0];
    const float* emb       = (const float*)d_in[1];
    const float* w_q       = (const float*)d_in[2];
    const float* w_kv      = (const float*)d_in[3];
    const float* w_o       = (const float*)d_in[4];
    const float* attn_nrm  = (const float*)d_in[5];
    const float* pattn_nrm = (const float*)d_in[6];
    const float* ffw_nrm   = (const float*)d_in[7];
    const float* pffw_nrm  = (const float*)d_in[8];
    const float* q_nrm     = (const float*)d_in[9];
    const float* k_nrm     = (const float*)d_in[10];
    const float* gate_w    = (const float*)d_in[11];
    const float* down_w    = (const float*)d_in[12];
    const float* final_nrm = (const float*)d_in[13];
    float* out = (float*)d_out;

    float *x, *h, *q, *kv, *gu;
    half *hh, *aoh, *gh, *wqh, *wkvh, *woh, *wgh, *wdh, *embh;
    cudaGetSymbolAddress((void**)&x,    g_x);
    cudaGetSymbolAddress((void**)&h,    g_h);
    cudaGetSymbolAddress((void**)&q,    g_q);
    cudaGetSymbolAddress((void**)&kv,   g_kv);
    cudaGetSymbolAddress((void**)&gu,   g_gu);
    cudaGetSymbolAddress((void**)&hh,   g_hh);
    cudaGetSymbolAddress((void**)&aoh,  g_aoh);
    cudaGetSymbolAddress((void**)&gh,   g_gh);
    cudaGetSymbolAddress((void**)&wqh,  gw_q);
    cudaGetSymbolAddress((void**)&wkvh, gw_kv);
    cudaGetSymbolAddress((void**)&woh,  gw_o);
    cudaGetSymbolAddress((void**)&wgh,  gw_gate);
    cudaGetSymbolAddress((void**)&wdh,  gw_down);
    cudaGetSymbolAddress((void**)&embh, g_embh);

    cudaFuncSetAttribute(hgemm_kernel,
                         cudaFuncAttributeMaxDynamicSharedMemorySize, SM_TOTAL);

    // transpose-convert weights -> [N][K] half (deterministic, every launch)
    { dim3 g(HDIM/32, DMODEL/32, LAYERS*NHEADS);
      tr_f2h_kernel<<<g, 256>>>(w_q, wqh, DMODEL, HDIM); }
    { dim3 g(HDIM/32, DMODEL/32, LAYERS*2*KVHEADS);
      tr_f2h_kernel<<<g, 256>>>(w_kv, wkvh, DMODEL, HDIM); }
    { dim3 g(DMODEL/32, (NHEADS*HDIM)/32, LAYERS);
      tr_f2h_kernel<<<g, 256>>>(w_o, woh, NHEADS*HDIM, DMODEL); }
    { dim3 g(FFN/32, DMODEL/32, LAYERS*2);
      tr_f2h_kernel<<<g, 256>>>(gate_w, wgh, DMODEL, FFN); }
    { dim3 g(DMODEL/32, FFN/32, LAYERS);
      tr_f2h_kernel<<<g, 256>>>(down_w, wdh, FFN, DMODEL); }
    // emb is already [V][D] = [N][K]
    { long n = (long)VOCAB * DMODEL;
      f2h_kernel<<<(unsigned)((n / 4 + 255) / 256), 256>>>(emb, embh, n); }

    // RoPE table
    rope_table_kernel<<<2 * SEQ * (HDIM/2) / 256, 256>>>();

    // embedding
    {
        long total = (long)MROWS * DMODEL;
        embed_kernel<<<(unsigned)((total + 255) / 256), 256>>>(tokens, emb, x, total);
    }

    for (int l = 0; l < LAYERS; l++) {
        int isLocal = (l % 2 == 0);
        int mode    = isLocal ? 0 : 1;

        // attn pre-norm -> half
        rmsnorm_h_kernel<<<MROWS, 256>>>(x, hh, attn_nrm + (size_t)l * DMODEL, DMODEL);

        // Q projection: single GEMM [4096,2304] x [2048,2304]^T
        {
            dim3 grid((NHEADS*HDIM) / 256, MROWS / 128);
            hgemm_kernel<<<grid, 256, SM_TOTAL>>>(hh, DMODEL,
                wqh + (size_t)l * NHEADS * DMODEL * HDIM, DMODEL,
                q, NHEADS * HDIM, DMODEL, 0);
        }
        // K+V combined: single GEMM [4096,2304] x [2048,2304]^T -> kv
        {
            dim3 grid((2*KVHEADS*HDIM) / 256, MROWS / 128);
            hgemm_kernel<<<grid, 256, SM_TOTAL>>>(hh, DMODEL,
                wkvh + (size_t)l * 2 * KVHEADS * DMODEL * HDIM, DMODEL,
                kv, 2 * KVHEADS * HDIM, DMODEL, 0);
        }
        // qk-norm
        rmsnorm_kernel<<<MROWS * NHEADS, 256>>>(q, q, q_nrm + (size_t)l * HDIM, HDIM);
        rmsnorm_kv_kernel<<<MROWS * KVHEADS, 256>>>(kv, k_nrm + (size_t)l * HDIM);
        // rope
        {
            long tq = (long)MROWS * NHEADS * (HDIM / 2);
            long tk = (long)MROWS * KVHEADS * (HDIM / 2);
            rope_q_kernel<<<(unsigned)((tq + 255) / 256), 256>>>(q, mode, tq);
            rope_kv_kernel<<<(unsigned)((tk + 255) / 256), 256>>>(kv, mode, tk);
        }
        // attention -> half
        {
            dim3 grid(SEQ / 16, NHEADS, BATCH);
            attn_kernel<<<grid, 256>>>(q, kv, aoh, isLocal);
        }
        // output projection: [4096,2048] x [2304,2048]^T
        {
            dim3 grid(DMODEL / 256, MROWS / 128);
            hgemm_kernel<<<grid, 256, SM_TOTAL>>>(aoh, NHEADS * HDIM,
                woh + (size_t)l * NHEADS * HDIM * DMODEL, NHEADS * HDIM,
                h, DMODEL, NHEADS * HDIM, 0);
        }
        add_rmsnorm_kernel<<<MROWS, 256>>>(x, h, pattn_nrm + (size_t)l * DMODEL, DMODEL);

        // MLP: gate+up combined [4096,2304] x [18432,2304]^T -> gu
        rmsnorm_h_kernel<<<MROWS, 256>>>(x, hh, ffw_nrm + (size_t)l * DMODEL, DMODEL);
        {
            dim3 grid((2*FFN) / 256, MROWS / 128);
            hgemm_kernel<<<grid, 256, SM_TOTAL>>>(hh, DMODEL,
                wgh + (size_t)(l * 2) * DMODEL * FFN, DMODEL,
                gu, 2 * FFN, DMODEL, 0);
        }
        {
            long total = (long)MROWS * FFN;
            geglu_kernel<<<(unsigned)((total + 255) / 256), 256>>>(gu, gh, total);
        }
        // down: [4096,9216] x [2304,9216]^T
        {
            dim3 grid(DMODEL / 256, MROWS / 128);
            hgemm_kernel<<<grid, 256, SM_TOTAL>>>(gh, FFN,
                wdh + (size_t)l * FFN * DMODEL, FFN,
                h, DMODEL, FFN, 0);
        }
        add_rmsnorm_kernel<<<MROWS, 256>>>(x, h, pffw_nrm + (size_t)l * DMODEL, DMODEL);
    }

    // final norm + tied-embedding decode with soft cap
    rmsnorm_h_kernel<<<MROWS, 256>>>(x, hh, final_nrm, DMODEL);
    {
        dim3 grid(VOCAB / 256, MROWS / 128);
        hgemm_kernel<<<grid, 256, SM_TOTAL>>>(hh, DMODEL,
            embh, DMODEL,
            out, VOCAB, DMODEL, 1);
    }
}